// round 11
// baseline (speedup 1.0000x reference)
#include <cuda_runtime.h>
#include <mma.h>
#include <math.h>

using namespace nvcuda;

#define Bsz 4096
#define Dd  1024
#define Rr  256

// ---------------- device scratch ----------------
static __device__ float g_hx[(size_t)Bsz * Rr];
static __device__ float g_hv[(size_t)Bsz * Rr];
static __device__ float g_fU[(size_t)Bsz * Rr];
static __device__ float g_P [(size_t)Bsz * Rr];
static __device__ float g_Sv[(size_t)Bsz * Rr];
static __device__ float g_Sx[(size_t)Bsz * Rr];
static __device__ float g_WU [(size_t)Rr * Rr];
static __device__ float g_WUp[(size_t)8 * Rr * Rr];

// ---------------- helpers ----------------
__device__ __forceinline__ void cp_async16(void* sptr, const void* gptr) {
    unsigned s = (unsigned)__cvta_generic_to_shared(sptr);
    asm volatile("cp.async.cg.shared.global [%0], [%1], 16;\n" :: "r"(s), "l"(gptr));
}
__device__ __forceinline__ void cp_commit() { asm volatile("cp.async.commit_group;\n"); }
template <int N> __device__ __forceinline__ void cp_wait() {
    asm volatile("cp.async.wait_group %0;\n" :: "n"(N));
}
__device__ __forceinline__ float tanh_fast(float x) {
    float y; asm("tanh.approx.f32 %0, %1;" : "=f"(y) : "f"(x)); return y;
}

typedef wmma::fragment<wmma::accumulator, 16, 16, 8, float> AccF;
typedef wmma::fragment<wmma::matrix_a, 16, 16, 8, wmma::precision::tf32, wmma::row_major> AF;
typedef wmma::fragment<wmma::matrix_b, 16, 16, 8, wmma::precision::tf32, wmma::row_major> BF;

// ===========================================================================
// kInit: hx = X@U, hv = V@U, fU = F@U (triple GEMM sharing U tile).
// Epilogue: P0 = tanh(hx)*hv^2.  Tile 128x64, grid (4, 32), 256 thr.
// ===========================================================================
constexpr int I_LDA = 40, I_LDU = 72;
constexpr int I_STAGE = 3 * 128 * I_LDA + 32 * I_LDU;
constexpr int I_SMEM  = 2 * I_STAGE * 4;

__global__ void __launch_bounds__(256, 1)
kInit(const float* __restrict__ X, const float* __restrict__ V,
      const float* __restrict__ Fin, const float* __restrict__ U)
{
    extern __shared__ float smem[];
    const int bn = blockIdx.x, bm = blockIdx.y;
    const int tid = threadIdx.x, warp = tid >> 5;
    const int wRow = (warp & 3) * 32, wCol = (warp >> 2) * 32;

    AccF acc[3][2][2];
    #pragma unroll
    for (int o = 0; o < 3; o++)
        #pragma unroll
        for (int i = 0; i < 2; i++)
            #pragma unroll
            for (int j = 0; j < 2; j++) wmma::fill_fragment(acc[o][i][j], 0.0f);

    const float* Ag[3] = { X + (size_t)bm * 128 * Dd,
                           V + (size_t)bm * 128 * Dd,
                           Fin + (size_t)bm * 128 * Dd };
    const float* Ug = U + bn * 64;

    auto load_stage = [&](int kt, int s) {
        float* st = smem + s * I_STAGE;
        const int k0 = kt * 32;
        #pragma unroll
        for (int o = 0; o < 3; o++) {
            float* sA = st + o * 128 * I_LDA;
            #pragma unroll
            for (int it = 0; it < 4; it++) {
                int t = tid + it * 256;
                int r = t >> 3, c4 = t & 7;
                cp_async16(&sA[r * I_LDA + c4 * 4], Ag[o] + (size_t)r * Dd + k0 + c4 * 4);
            }
        }
        float* sU = st + 3 * 128 * I_LDA;
        #pragma unroll
        for (int it = 0; it < 2; it++) {
            int t = tid + it * 256;
            int r = t >> 4, c4 = t & 15;
            cp_async16(&sU[r * I_LDU + c4 * 4], Ug + (size_t)(k0 + r) * Rr + c4 * 4);
        }
        cp_commit();
    };

    constexpr int KT = Dd / 32;
    load_stage(0, 0);
    for (int kt = 0; kt < KT; kt++) {
        if (kt + 1 < KT) { load_stage(kt + 1, (kt + 1) & 1); cp_wait<1>(); }
        else             { cp_wait<0>(); }
        __syncthreads();
        const float* st = smem + (kt & 1) * I_STAGE;
        const float* sU = st + 3 * 128 * I_LDA;
        #pragma unroll
        for (int kk = 0; kk < 32; kk += 8) {
            AF af[3][2]; BF bu[2];
            #pragma unroll
            for (int o = 0; o < 3; o++)
                #pragma unroll
                for (int i = 0; i < 2; i++)
                    wmma::load_matrix_sync(af[o][i],
                        st + o * 128 * I_LDA + (wRow + i * 16) * I_LDA + kk, I_LDA);
            #pragma unroll
            for (int j = 0; j < 2; j++)
                wmma::load_matrix_sync(bu[j], sU + kk * I_LDU + wCol + j * 16, I_LDU);
            #pragma unroll
            for (int o = 0; o < 3; o++)
                #pragma unroll
                for (int i = 0; i < 2; i++)
                    #pragma unroll
                    for (int j = 0; j < 2; j++)
                        wmma::mma_sync(acc[o][i][j], af[o][i], bu[j], acc[o][i][j]);
        }
        __syncthreads();
    }

    #pragma unroll
    for (int i = 0; i < 2; i++)
        #pragma unroll
        for (int j = 0; j < 2; j++) {
            size_t off = (size_t)(bm * 128 + wRow + i * 16) * Rr + bn * 64 + wCol + j * 16;
            wmma::store_matrix_sync(g_hx + off, acc[0][i][j], Rr, wmma::mem_row_major);
            wmma::store_matrix_sync(g_hv + off, acc[1][i][j], Rr, wmma::mem_row_major);
            wmma::store_matrix_sync(g_fU + off, acc[2][i][j], Rr, wmma::mem_row_major);
            #pragma unroll
            for (int e = 0; e < acc[0][i][j].num_elements; e++) {
                float h = acc[1][i][j].x[e];
                acc[0][i][j].x[e] = tanh_fast(acc[0][i][j].x[e]) * h * h;
            }
            wmma::store_matrix_sync(g_P + off, acc[0][i][j], Rr, wmma::mem_row_major);
        }
}

// ===========================================================================
// kWU: WU = W@U  [256,1024]@[1024,256], split-K (8 x 128). Grid (2,2,8).
// ===========================================================================
constexpr int W_LDA = 40, W_LDB = 136;
constexpr int W_STAGE = 128 * W_LDA + 32 * W_LDB;
constexpr int W_SMEM  = 2 * W_STAGE * 4;

__global__ void __launch_bounds__(256, 1)
kWU(const float* __restrict__ W, const float* __restrict__ U)
{
    extern __shared__ float smem[];
    const int bnn = blockIdx.x, bm = blockIdx.y, kz = blockIdx.z;
    const int tid = threadIdx.x, warp = tid >> 5;
    const int wRow = (warp & 3) * 32, wCol = (warp >> 2) * 64;

    AccF acc[2][4];
    #pragma unroll
    for (int i = 0; i < 2; i++)
        #pragma unroll
        for (int j = 0; j < 4; j++) wmma::fill_fragment(acc[i][j], 0.0f);

    const float* Ag = W + (size_t)bm * 128 * Dd + kz * 128;
    const float* Bg = U + (size_t)kz * 128 * Rr + bnn * 128;

    auto load_stage = [&](int kt, int s) {
        float* sA = smem + s * W_STAGE;
        float* sB = sA + 128 * W_LDA;
        const int k0 = kt * 32;
        #pragma unroll
        for (int it = 0; it < 4; it++) {
            int t = tid + it * 256;
            int r = t >> 3, c4 = t & 7;
            cp_async16(&sA[r * W_LDA + c4 * 4], Ag + (size_t)r * Dd + k0 + c4 * 4);
        }
        #pragma unroll
        for (int it = 0; it < 4; it++) {
            int t = tid + it * 256;
            int r = t >> 5, c4 = t & 31;
            cp_async16(&sB[r * W_LDB + c4 * 4], Bg + (size_t)(k0 + r) * Rr + c4 * 4);
        }
        cp_commit();
    };

    constexpr int KT = 4;
    load_stage(0, 0);
    for (int kt = 0; kt < KT; kt++) {
        if (kt + 1 < KT) { load_stage(kt + 1, (kt + 1) & 1); cp_wait<1>(); }
        else             { cp_wait<0>(); }
        __syncthreads();
        const float* sA = smem + (kt & 1) * W_STAGE;
        const float* sB = sA + 128 * W_LDA;
        #pragma unroll
        for (int kk = 0; kk < 32; kk += 8) {
            AF af[2]; BF bf[4];
            #pragma unroll
            for (int i = 0; i < 2; i++)
                wmma::load_matrix_sync(af[i], sA + (wRow + i * 16) * W_LDA + kk, W_LDA);
            #pragma unroll
            for (int j = 0; j < 4; j++)
                wmma::load_matrix_sync(bf[j], sB + kk * W_LDB + wCol + j * 16, W_LDB);
            #pragma unroll
            for (int i = 0; i < 2; i++)
                #pragma unroll
                for (int j = 0; j < 4; j++)
                    wmma::mma_sync(acc[i][j], af[i], bf[j], acc[i][j]);
        }
        __syncthreads();
    }

    float* out = g_WUp + (size_t)kz * Rr * Rr;
    #pragma unroll
    for (int i = 0; i < 2; i++)
        #pragma unroll
        for (int j = 0; j < 4; j++)
            wmma::store_matrix_sync(out + (size_t)(bm * 128 + wRow + i * 16) * Rr
                                        + bnn * 128 + wCol + j * 16,
                                    acc[i][j], Rr, wmma::mem_row_major);
}

__global__ void kRed() {
    int i = blockIdx.x * 256 + threadIdx.x;
    float s = 0.0f;
    #pragma unroll
    for (int z = 0; z < 8; z++) s += g_WUp[(size_t)z * Rr * Rr + i];
    g_WU[i] = s;
}

// ===========================================================================
// kSteps: persistent — ALL 15 half-steps in one launch.
// Grid 128 CTAs x 256 thr; CTA owns 32 batch rows; rows are independent
// (K-dim of P@WU is R), so no inter-CTA sync. State (hx,hv,fU,P) smem-resident;
// Sv/Sx in registers; WU streamed per step (cp.async, 2 buffers).
// ===========================================================================
constexpr int PLD = 264;                    // padded row stride
constexpr int PS_TILE = 32 * PLD;           // 8448 floats per region
constexpr int PS_SMEM = 6 * PS_TILE * 4;    // 202752 B

__global__ void __launch_bounds__(256, 1)
kSteps()
{
    extern __shared__ float sm[];
    float* sHx = sm;
    float* sHv = sm + PS_TILE;
    float* sFu = sm + 2 * PS_TILE;
    float* sP  = sm + 3 * PS_TILE;
    float* sWb = sm + 4 * PS_TILE;          // 2 buffers of PS_TILE

    const int tid  = threadIdx.x;
    const int warp = tid >> 5;
    const int wm = warp & 1, wn = warp >> 1;   // 2 warps in M, 4 in N
    const int base = blockIdx.x * 32;

    // ---- load state (once) ----
    #pragma unroll
    for (int it = 0; it < 8; it++) {
        int u = tid + it * 256;
        int r = u >> 6, c = (u & 63) * 4;
        size_t g = (size_t)(base + r) * Rr + c;
        *(float4*)&sHx[r * PLD + c] = *(const float4*)(g_hx + g);
        *(float4*)&sHv[r * PLD + c] = *(const float4*)(g_hv + g);
        *(float4*)&sFu[r * PLD + c] = *(const float4*)(g_fU + g);
        *(float4*)&sP [r * PLD + c] = *(const float4*)(g_P  + g);
    }
    __syncthreads();

    // ---- register sums, init from P0 (Sv=P0, Sx=8*P0) ----
    const int rt  = tid >> 3;
    const int ct0 = (tid & 7) * 4;
    float Sv[32], Sx[32];
    #pragma unroll
    for (int j = 0; j < 8; j++) {
        float4 p = *(float4*)&sP[rt * PLD + ct0 + j * 32];
        Sv[j*4+0] = p.x; Sv[j*4+1] = p.y; Sv[j*4+2] = p.z; Sv[j*4+3] = p.w;
        Sx[j*4+0] = 8.0f*p.x; Sx[j*4+1] = 8.0f*p.y; Sx[j*4+2] = 8.0f*p.z; Sx[j*4+3] = 8.0f*p.w;
    }

    auto loadW = [&](int kt, int b) {
        float* dst = sWb + b * PS_TILE;
        #pragma unroll
        for (int it = 0; it < 8; it++) {
            int u = tid + it * 256;
            int r = u >> 6, c = (u & 63) * 4;
            cp_async16(&dst[r * PLD + c], g_WU + (size_t)(kt * 32 + r) * Rr + c);
        }
        cp_commit();
    };

    loadW(0, 0);
    #pragma unroll 1
    for (int t = 0; t < 15; t++) {
        // ---- GEMM: gamma[32,256] = P[32,256] @ WU[256,256] ----
        AccF acc[4];
        #pragma unroll
        for (int j = 0; j < 4; j++) wmma::fill_fragment(acc[j], 0.0f);

        #pragma unroll 1
        for (int kt = 0; kt < 8; kt++) {
            if (kt + 1 < 8) { loadW(kt + 1, (kt + 1) & 1); cp_wait<1>(); }
            else            { cp_wait<0>(); }
            __syncthreads();
            const float* sW = sWb + (kt & 1) * PS_TILE;
            #pragma unroll
            for (int kk = 0; kk < 32; kk += 8) {
                AF a;
                wmma::load_matrix_sync(a, &sP[(wm * 16) * PLD + kt * 32 + kk], PLD);
                #pragma unroll
                for (int j = 0; j < 4; j++) {
                    BF bf;
                    wmma::load_matrix_sync(bf, &sW[kk * PLD + wn * 64 + j * 16], PLD);
                    wmma::mma_sync(acc[j], a, bf, acc[j]);
                }
            }
            __syncthreads();
        }

        // ---- stage gamma in buffer 0 (free until next step's loadW(0,0)) ----
        float* sG = sWb;
        #pragma unroll
        for (int j = 0; j < 4; j++)
            wmma::store_matrix_sync(&sG[(wm * 16) * PLD + wn * 64 + j * 16],
                                    acc[j], PLD, wmma::mem_row_major);
        __syncthreads();

        // ---- fused elementwise half-step ----
        const float wq   = (float)(7 - (t >> 1));
        const bool updx  = (t & 1) == 0;
        #pragma unroll
        for (int j = 0; j < 8; j++) {
            int o = rt * PLD + ct0 + j * 32;
            float4 g  = *(float4*)&sG[o];
            float4 fu = *(float4*)&sFu[o];
            float4 hv = *(float4*)&sHv[o];
            hv.x += 0.005f * (fu.x - g.x);
            hv.y += 0.005f * (fu.y - g.y);
            hv.z += 0.005f * (fu.z - g.z);
            hv.w += 0.005f * (fu.w - g.w);
            *(float4*)&sHv[o] = hv;
            float4 hx = *(float4*)&sHx[o];
            if (updx) {
                hx.x += 0.01f * hv.x; hx.y += 0.01f * hv.y;
                hx.z += 0.01f * hv.z; hx.w += 0.01f * hv.w;
                *(float4*)&sHx[o] = hx;
            }
            float4 p;
            p.x = tanh_fast(hx.x) * hv.x * hv.x;
            p.y = tanh_fast(hx.y) * hv.y * hv.y;
            p.z = tanh_fast(hx.z) * hv.z * hv.z;
            p.w = tanh_fast(hx.w) * hv.w * hv.w;
            *(float4*)&sP[o] = p;
            Sv[j*4+0] += p.x; Sv[j*4+1] += p.y; Sv[j*4+2] += p.z; Sv[j*4+3] += p.w;
            Sx[j*4+0] += wq * p.x; Sx[j*4+1] += wq * p.y;
            Sx[j*4+2] += wq * p.z; Sx[j*4+3] += wq * p.w;
        }
        __syncthreads();
        if (t + 1 < 15) loadW(0, 0);
    }

    // ---- write sums ----
    #pragma unroll
    for (int j = 0; j < 8; j++) {
        size_t g = (size_t)(base + rt) * Rr + ct0 + j * 32;
        *(float4*)(g_Sv + g) = make_float4(Sv[j*4+0], Sv[j*4+1], Sv[j*4+2], Sv[j*4+3]);
        *(float4*)(g_Sx + g) = make_float4(Sx[j*4+0], Sx[j*4+1], Sx[j*4+2], Sx[j*4+3]);
    }
}

// ===========================================================================
// kFinal: dual GEMM (Sx, Sv) @ W, fused output. Tile 128x64, grid (16,32).
// ===========================================================================
constexpr int F_LDA = 40, F_LDB = 72, F_LDG = 68;
constexpr int F_STAGE = 2 * 128 * F_LDA + 32 * F_LDB;
constexpr int F_SMEM_F = (2 * F_STAGE > 2 * 128 * F_LDG) ? 2 * F_STAGE : 2 * 128 * F_LDG;
constexpr int F_SMEM   = F_SMEM_F * 4;

__global__ void __launch_bounds__(256, 1)
kFinal(const float* __restrict__ W, const float* __restrict__ x0,
       const float* __restrict__ v0, const float* __restrict__ Fin,
       float* __restrict__ Xw, float* __restrict__ Vw)
{
    extern __shared__ float smem[];
    const int bn = blockIdx.x, bm = blockIdx.y;
    const int tid = threadIdx.x, warp = tid >> 5;
    const int wRow = (warp & 3) * 32, wCol = (warp >> 2) * 32;

    AccF acc[2][2][2];
    #pragma unroll
    for (int o = 0; o < 2; o++)
        #pragma unroll
        for (int i = 0; i < 2; i++)
            #pragma unroll
            for (int j = 0; j < 2; j++) wmma::fill_fragment(acc[o][i][j], 0.0f);

    const float* Ag[2] = { g_Sx + (size_t)bm * 128 * Rr, g_Sv + (size_t)bm * 128 * Rr };
    const float* Bg = W + bn * 64;

    auto load_stage = [&](int kt, int s) {
        float* st = smem + s * F_STAGE;
        const int k0 = kt * 32;
        #pragma unroll
        for (int o = 0; o < 2; o++) {
            float* sA = st + o * 128 * F_LDA;
            #pragma unroll
            for (int it = 0; it < 4; it++) {
                int t = tid + it * 256;
                int r = t >> 3, c4 = t & 7;
                cp_async16(&sA[r * F_LDA + c4 * 4], Ag[o] + (size_t)r * Rr + k0 + c4 * 4);
            }
        }
        float* sB = st + 2 * 128 * F_LDA;
        #pragma unroll
        for (int it = 0; it < 2; it++) {
            int t = tid + it * 256;
            int r = t >> 4, c4 = t & 15;
            cp_async16(&sB[r * F_LDB + c4 * 4], Bg + (size_t)(k0 + r) * Dd + c4 * 4);
        }
        cp_commit();
    };

    constexpr int KT = Rr / 32;
    load_stage(0, 0);
    for (int kt = 0; kt < KT; kt++) {
        if (kt + 1 < KT) { load_stage(kt + 1, (kt + 1) & 1); cp_wait<1>(); }
        else             { cp_wait<0>(); }
        __syncthreads();
        const float* st = smem + (kt & 1) * F_STAGE;
        const float* sB = st + 2 * 128 * F_LDA;
        #pragma unroll
        for (int kk = 0; kk < 32; kk += 8) {
            AF af[2][2]; BF bf[2];
            #pragma unroll
            for (int o = 0; o < 2; o++)
                #pragma unroll
                for (int i = 0; i < 2; i++)
                    wmma::load_matrix_sync(af[o][i],
                        st + o * 128 * F_LDA + (wRow + i * 16) * F_LDA + kk, F_LDA);
            #pragma unroll
            for (int j = 0; j < 2; j++)
                wmma::load_matrix_sync(bf[j], sB + kk * F_LDB + wCol + j * 16, F_LDB);
            #pragma unroll
            for (int o = 0; o < 2; o++)
                #pragma unroll
                for (int i = 0; i < 2; i++)
                    #pragma unroll
                    for (int j = 0; j < 2; j++)
                        wmma::mma_sync(acc[o][i][j], af[o][i], bf[j], acc[o][i][j]);
        }
        __syncthreads();
    }

    float* sGx = smem;
    float* sGv = smem + 128 * F_LDG;
    #pragma unroll
    for (int i = 0; i < 2; i++)
        #pragma unroll
        for (int j = 0; j < 2; j++) {
            wmma::store_matrix_sync(&sGx[(wRow + i * 16) * F_LDG + wCol + j * 16],
                                    acc[0][i][j], F_LDG, wmma::mem_row_major);
            wmma::store_matrix_sync(&sGv[(wRow + i * 16) * F_LDG + wCol + j * 16],
                                    acc[1][i][j], F_LDG, wmma::mem_row_major);
        }
    __syncthreads();

    const float c_xv = 0.08f;        // 8*dt
    const float c_xf = 0.0032f;      // 64*dt*hdt
    const float c_xg = 5e-5f;        // dt*hdt
    const float c_vf = 0.08f;        // 16*hdt
    const float c_vg = 0.005f;       // hdt
    #pragma unroll
    for (int it = 0; it < 8; it++) {
        int u = tid + it * 256;
        int r = u >> 4, c4 = u & 15;
        float4 gx = *(float4*)&sGx[r * F_LDG + c4 * 4];
        float4 gv = *(float4*)&sGv[r * F_LDG + c4 * 4];
        size_t idx = (size_t)(bm * 128 + r) * Dd + bn * 64 + c4 * 4;
        float4 x = *(const float4*)(x0 + idx);
        float4 v = *(const float4*)(v0 + idx);
        float4 f = *(const float4*)(Fin + idx);
        float4 xo, vo;
        xo.x = x.x + c_xv * v.x + c_xf * f.x - c_xg * gx.x;
        xo.y = x.y + c_xv * v.y + c_xf * f.y - c_xg * gx.y;
        xo.z = x.z + c_xv * v.z + c_xf * f.z - c_xg * gx.z;
        xo.w = x.w + c_xv * v.w + c_xf * f.w - c_xg * gx.w;
        vo.x = v.x + c_vf * f.x - c_vg * gv.x;
        vo.y = v.y + c_vf * f.y - c_vg * gv.y;
        vo.z = v.z + c_vf * f.z - c_vg * gv.z;
        vo.w = v.w + c_vf * f.w - c_vg * gv.w;
        *(float4*)(Xw + idx) = xo;
        *(float4*)(Vw + idx) = vo;
    }
}

// ===========================================================================
extern "C" void kernel_launch(void* const* d_in, const int* in_sizes, int n_in,
                              void* d_out, int out_size)
{
    const float* x0 = (const float*)d_in[0];
    const float* v0 = (const float*)d_in[1];
    const float* F  = (const float*)d_in[2];
    const float* U  = (const float*)d_in[3];
    const float* W  = (const float*)d_in[4];

    float* Xw = (float*)d_out;
    float* Vw = Xw + (size_t)Bsz * Dd;

    cudaFuncSetAttribute(kInit,  cudaFuncAttributeMaxDynamicSharedMemorySize, I_SMEM);
    cudaFuncSetAttribute(kWU,    cudaFuncAttributeMaxDynamicSharedMemorySize, W_SMEM);
    cudaFuncSetAttribute(kSteps, cudaFuncAttributeMaxDynamicSharedMemorySize, PS_SMEM);
    cudaFuncSetAttribute(kFinal, cudaFuncAttributeMaxDynamicSharedMemorySize, F_SMEM);

    dim3 blk(256);

    kWU<<<dim3(2, 2, 8), blk, W_SMEM>>>(W, U);
    kRed<<<Rr * Rr / 256, 256>>>();
    kInit<<<dim3(4, 32), blk, I_SMEM>>>(x0, v0, F, U);
    kSteps<<<128, blk, PS_SMEM>>>();
    kFinal<<<dim3(16, 32), blk, F_SMEM>>>(W, x0, v0, F, Xw, Vw);
}

// round 12
// speedup vs baseline: 3.6225x; 3.6225x over previous
#include <cuda_runtime.h>
#include <mma.h>
#include <cuda_fp16.h>
#include <math.h>

using namespace nvcuda;

#define Bsz 4096
#define Dd  1024
#define Rr  256

// ---------------- device scratch ----------------
static __device__ float  g_hx[(size_t)Bsz * Rr];
static __device__ float  g_hv[(size_t)Bsz * Rr];
static __device__ float  g_fU[(size_t)Bsz * Rr];
static __device__ float  g_P [(size_t)Bsz * Rr];
static __device__ float  g_WUp[(size_t)8 * Rr * Rr];
static __device__ __align__(16) __half g_Xh[(size_t)Bsz * Dd];
static __device__ __align__(16) __half g_Vh[(size_t)Bsz * Dd];
static __device__ __align__(16) __half g_Fh[(size_t)Bsz * Dd];
static __device__ __align__(16) __half g_Uh[(size_t)Dd * Rr];
static __device__ __align__(16) __half g_Wh[(size_t)Rr * Dd];
static __device__ __align__(16) __half g_WUh[(size_t)Rr * Rr];
static __device__ __align__(16) __half g_Svh[(size_t)Bsz * Rr];
static __device__ __align__(16) __half g_Sxh[(size_t)Bsz * Rr];

// ---------------- helpers ----------------
__device__ __forceinline__ void cp_async16(void* sptr, const void* gptr) {
    unsigned s = (unsigned)__cvta_generic_to_shared(sptr);
    asm volatile("cp.async.cg.shared.global [%0], [%1], 16;\n" :: "r"(s), "l"(gptr));
}
__device__ __forceinline__ void cp_commit() { asm volatile("cp.async.commit_group;\n"); }
template <int N> __device__ __forceinline__ void cp_wait() {
    asm volatile("cp.async.wait_group %0;\n" :: "n"(N));
}
__device__ __forceinline__ float tanh_fast(float x) {
    float y; asm("tanh.approx.f32 %0, %1;" : "=f"(y) : "f"(x)); return y;
}

typedef wmma::fragment<wmma::accumulator, 16, 16, 16, float> AccH;
typedef wmma::fragment<wmma::matrix_a, 16, 16, 16, __half, wmma::row_major> AH;
typedef wmma::fragment<wmma::matrix_b, 16, 16, 16, __half, wmma::row_major> BH;

// ===========================================================================
// kCvt: fp32 -> fp16  (vectorized)
// ===========================================================================
__global__ void kCvt(const float4* __restrict__ in, __half2* __restrict__ out, int n4) {
    int i = blockIdx.x * 256 + threadIdx.x;
    if (i < n4) {
        float4 f = in[i];
        out[2 * i]     = __floats2half2_rn(f.x, f.y);
        out[2 * i + 1] = __floats2half2_rn(f.z, f.w);
    }
}

// ===========================================================================
// kWU: WU = Wh@Uh  [256,1024]@[1024,256], split-K (8 x 128). Grid (2,2,8).
// fp16 operands, fp32 partials -> g_WUp; kRed sums -> g_WUh (half).
// ===========================================================================
constexpr int W_LDA = 72;    // 64+8 halves
constexpr int W_LDB = 136;   // 128+8 halves
constexpr int W_STAGE_H = 128 * W_LDA + 64 * W_LDB;   // 17920 halves
constexpr int W_SMEM = 2 * W_STAGE_H * 2;             // 71680 B

__global__ void __launch_bounds__(256, 1)
kWU()
{
    extern __shared__ __half smh[];
    const int bnn = blockIdx.x, bm = blockIdx.y, kz = blockIdx.z;
    const int tid = threadIdx.x, warp = tid >> 5;
    const int wRow = (warp & 3) * 32, wCol = (warp >> 2) * 64;

    AccH acc[2][4];
    #pragma unroll
    for (int i = 0; i < 2; i++)
        #pragma unroll
        for (int j = 0; j < 4; j++) wmma::fill_fragment(acc[i][j], 0.0f);

    const __half* Ag = g_Wh + (size_t)bm * 128 * Dd + kz * 128;
    const __half* Bg = g_Uh + (size_t)kz * 128 * Rr + bnn * 128;

    auto load_stage = [&](int kt, int s) {
        __half* sA = smh + s * W_STAGE_H;
        __half* sB = sA + 128 * W_LDA;
        const int k0 = kt * 64;
        #pragma unroll
        for (int it = 0; it < 4; it++) {
            int u = tid + it * 256;
            int r = u >> 3, c8 = u & 7;
            cp_async16(&sA[r * W_LDA + c8 * 8], Ag + (size_t)r * Dd + k0 + c8 * 8);
        }
        #pragma unroll
        for (int it = 0; it < 4; it++) {
            int u = tid + it * 256;
            int r = u >> 4, c8 = u & 15;
            cp_async16(&sB[r * W_LDB + c8 * 8], Bg + (size_t)(k0 + r) * Rr + c8 * 8);
        }
        cp_commit();
    };

    constexpr int KT = 2;
    load_stage(0, 0);
    for (int kt = 0; kt < KT; kt++) {
        if (kt + 1 < KT) { load_stage(kt + 1, (kt + 1) & 1); cp_wait<1>(); }
        else             { cp_wait<0>(); }
        __syncthreads();
        const __half* sA = smh + (kt & 1) * W_STAGE_H;
        const __half* sB = sA + 128 * W_LDA;
        #pragma unroll
        for (int kk = 0; kk < 4; kk++) {
            AH af[2]; BH bf[4];
            #pragma unroll
            for (int i = 0; i < 2; i++)
                wmma::load_matrix_sync(af[i], sA + (wRow + i * 16) * W_LDA + kk * 16, W_LDA);
            #pragma unroll
            for (int j = 0; j < 4; j++)
                wmma::load_matrix_sync(bf[j], sB + (kk * 16) * W_LDB + wCol + j * 16, W_LDB);
            #pragma unroll
            for (int i = 0; i < 2; i++)
                #pragma unroll
                for (int j = 0; j < 4; j++)
                    wmma::mma_sync(acc[i][j], af[i], bf[j], acc[i][j]);
        }
        __syncthreads();
    }

    float* out = g_WUp + (size_t)kz * Rr * Rr;
    #pragma unroll
    for (int i = 0; i < 2; i++)
        #pragma unroll
        for (int j = 0; j < 4; j++)
            wmma::store_matrix_sync(out + (size_t)(bm * 128 + wRow + i * 16) * Rr
                                        + bnn * 128 + wCol + j * 16,
                                    acc[i][j], Rr, wmma::mem_row_major);
}

__global__ void kRed() {
    int i = blockIdx.x * 256 + threadIdx.x;
    float s = 0.0f;
    #pragma unroll
    for (int z = 0; z < 8; z++) s += g_WUp[(size_t)z * Rr * Rr + i];
    g_WUh[i] = __float2half_rn(s);
}

// ===========================================================================
// kInit: hx = X@U, hv = V@U, fU = F@U (fp16 triple GEMM sharing U tile).
// Epilogue: P0 = tanh(hx)*hv^2 (fp32 out).  Tile 128x64, BK=64, grid (4,32).
// ===========================================================================
constexpr int I_LDA = 72;    // 64+8 halves
constexpr int I_LDU = 72;
constexpr int I_STAGE_H = 3 * 128 * I_LDA + 64 * I_LDU;   // 32256 halves
constexpr int I_SMEM = 2 * I_STAGE_H * 2;                 // 129024 B

__global__ void __launch_bounds__(256, 1)
kInit()
{
    extern __shared__ __half smh[];
    const int bn = blockIdx.x, bm = blockIdx.y;
    const int tid = threadIdx.x, warp = tid >> 5;
    const int wRow = (warp & 3) * 32, wCol = (warp >> 2) * 32;

    AccH acc[3][2][2];
    #pragma unroll
    for (int o = 0; o < 3; o++)
        #pragma unroll
        for (int i = 0; i < 2; i++)
            #pragma unroll
            for (int j = 0; j < 2; j++) wmma::fill_fragment(acc[o][i][j], 0.0f);

    const __half* Ag[3] = { g_Xh + (size_t)bm * 128 * Dd,
                            g_Vh + (size_t)bm * 128 * Dd,
                            g_Fh + (size_t)bm * 128 * Dd };
    const __half* Ug = g_Uh + bn * 64;

    auto load_stage = [&](int kt, int s) {
        __half* st = smh + s * I_STAGE_H;
        const int k0 = kt * 64;
        #pragma unroll
        for (int o = 0; o < 3; o++) {
            __half* sA = st + o * 128 * I_LDA;
            #pragma unroll
            for (int it = 0; it < 4; it++) {
                int u = tid + it * 256;
                int r = u >> 3, c8 = u & 7;
                cp_async16(&sA[r * I_LDA + c8 * 8], Ag[o] + (size_t)r * Dd + k0 + c8 * 8);
            }
        }
        __half* sU = st + 3 * 128 * I_LDA;
        #pragma unroll
        for (int it = 0; it < 2; it++) {
            int u = tid + it * 256;
            int r = u >> 3, c8 = u & 7;
            cp_async16(&sU[r * I_LDU + c8 * 8], Ug + (size_t)(k0 + r) * Rr + c8 * 8);
        }
        cp_commit();
    };

    constexpr int KT = Dd / 64;   // 16
    load_stage(0, 0);
    for (int kt = 0; kt < KT; kt++) {
        if (kt + 1 < KT) { load_stage(kt + 1, (kt + 1) & 1); cp_wait<1>(); }
        else             { cp_wait<0>(); }
        __syncthreads();
        const __half* st = smh + (kt & 1) * I_STAGE_H;
        const __half* sU = st + 3 * 128 * I_LDA;
        #pragma unroll
        for (int kk = 0; kk < 4; kk++) {
            AH af[3][2]; BH bu[2];
            #pragma unroll
            for (int o = 0; o < 3; o++)
                #pragma unroll
                for (int i = 0; i < 2; i++)
                    wmma::load_matrix_sync(af[o][i],
                        st + o * 128 * I_LDA + (wRow + i * 16) * I_LDA + kk * 16, I_LDA);
            #pragma unroll
            for (int j = 0; j < 2; j++)
                wmma::load_matrix_sync(bu[j], sU + (kk * 16) * I_LDU + wCol + j * 16, I_LDU);
            #pragma unroll
            for (int o = 0; o < 3; o++)
                #pragma unroll
                for (int i = 0; i < 2; i++)
                    #pragma unroll
                    for (int j = 0; j < 2; j++)
                        wmma::mma_sync(acc[o][i][j], af[o][i], bu[j], acc[o][i][j]);
        }
        __syncthreads();
    }

    #pragma unroll
    for (int i = 0; i < 2; i++)
        #pragma unroll
        for (int j = 0; j < 2; j++) {
            size_t off = (size_t)(bm * 128 + wRow + i * 16) * Rr + bn * 64 + wCol + j * 16;
            wmma::store_matrix_sync(g_hx + off, acc[0][i][j], Rr, wmma::mem_row_major);
            wmma::store_matrix_sync(g_hv + off, acc[1][i][j], Rr, wmma::mem_row_major);
            wmma::store_matrix_sync(g_fU + off, acc[2][i][j], Rr, wmma::mem_row_major);
            #pragma unroll
            for (int e = 0; e < acc[0][i][j].num_elements; e++) {
                float h = acc[1][i][j].x[e];
                acc[0][i][j].x[e] = tanh_fast(acc[0][i][j].x[e]) * h * h;
            }
            wmma::store_matrix_sync(g_P + off, acc[0][i][j], Rr, wmma::mem_row_major);
        }
}

// ===========================================================================
// kSteps: persistent — all 15 half-steps. 128 CTAs x 256 thr; CTA owns 32 rows.
// State hx/hv/fU fp32 in smem; P half in smem; Sv/Sx fp32 regs -> half out.
// WU (half) streamed in 64-row chunks, double buffered.
// ===========================================================================
constexpr int PLD = 264;
constexpr size_t PSB_HX = 0;
constexpr size_t PSB_HV = PSB_HX + 32 * PLD * 4;
constexpr size_t PSB_FU = PSB_HV + 32 * PLD * 4;
constexpr size_t PSB_P  = PSB_FU + 32 * PLD * 4;            // half, 32*264*2
constexpr size_t PSB_W  = PSB_P + 32 * PLD * 2;             // half, 2 x 64*264*2
constexpr size_t PS_SMEM = PSB_W + 2 * 64 * PLD * 2;        // 185856 B

__global__ void __launch_bounds__(256, 1)
kSteps()
{
    extern __shared__ char smc[];
    float*  sHx = (float*)(smc + PSB_HX);
    float*  sHv = (float*)(smc + PSB_HV);
    float*  sFu = (float*)(smc + PSB_FU);
    __half* sP  = (__half*)(smc + PSB_P);
    __half* sWh = (__half*)(smc + PSB_W);

    const int tid  = threadIdx.x;
    const int warp = tid >> 5;
    const int wm = warp & 1, wn = warp >> 1;   // 2 warps M x 4 warps N
    const int base = blockIdx.x * 32;

    // ---- load state once ----
    #pragma unroll
    for (int it = 0; it < 8; it++) {
        int u = tid + it * 256;
        int r = u >> 6, c = (u & 63) * 4;
        size_t g = (size_t)(base + r) * Rr + c;
        *(float4*)&sHx[r * PLD + c] = *(const float4*)(g_hx + g);
        *(float4*)&sHv[r * PLD + c] = *(const float4*)(g_hv + g);
        *(float4*)&sFu[r * PLD + c] = *(const float4*)(g_fU + g);
        float4 p = *(const float4*)(g_P + g);
        *(__half2*)&sP[r * PLD + c]     = __floats2half2_rn(p.x, p.y);
        *(__half2*)&sP[r * PLD + c + 2] = __floats2half2_rn(p.z, p.w);
    }
    __syncthreads();

    // ---- register sums, init from P0 (Sv=P0, Sx=8*P0) ----
    const int rt  = tid >> 3;
    const int ct0 = (tid & 7) * 4;
    float Sv[32], Sx[32];
    #pragma unroll
    for (int j = 0; j < 8; j++) {
        int o = rt * PLD + ct0 + j * 32;
        #pragma unroll
        for (int q = 0; q < 4; q++) {
            float p = __half2float(sP[o + q]);
            Sv[j*4+q] = p; Sx[j*4+q] = 8.0f * p;
        }
    }

    auto loadW = [&](int kt, int b) {
        __half* dst = sWh + b * 64 * PLD;
        #pragma unroll
        for (int it = 0; it < 8; it++) {
            int u = tid + it * 256;
            int r = u >> 5, c8 = u & 31;
            cp_async16(&dst[r * PLD + c8 * 8],
                       g_WUh + (size_t)(kt * 64 + r) * Rr + c8 * 8);
        }
        cp_commit();
    };

    loadW(0, 0);
    #pragma unroll 1
    for (int t = 0; t < 15; t++) {
        AccH acc[4];
        #pragma unroll
        for (int j = 0; j < 4; j++) wmma::fill_fragment(acc[j], 0.0f);

        #pragma unroll 1
        for (int kt = 0; kt < 4; kt++) {
            if (kt + 1 < 4) { loadW(kt + 1, (kt + 1) & 1); cp_wait<1>(); }
            else            { cp_wait<0>(); }
            __syncthreads();
            const __half* sW = sWh + (kt & 1) * 64 * PLD;
            #pragma unroll
            for (int kk = 0; kk < 4; kk++) {
                AH a;
                wmma::load_matrix_sync(a, &sP[(wm * 16) * PLD + kt * 64 + kk * 16], PLD);
                #pragma unroll
                for (int j = 0; j < 4; j++) {
                    BH bf;
                    wmma::load_matrix_sync(bf, &sW[(kk * 16) * PLD + wn * 64 + j * 16], PLD);
                    wmma::mma_sync(acc[j], a, bf, acc[j]);
                }
            }
            __syncthreads();
        }

        // stage gamma (fp32) into W buffer 0 (exact fit, free until next loadW(0,0))
        float* sG = (float*)sWh;
        #pragma unroll
        for (int j = 0; j < 4; j++)
            wmma::store_matrix_sync(&sG[(wm * 16) * PLD + wn * 64 + j * 16],
                                    acc[j], PLD, wmma::mem_row_major);
        __syncthreads();

        const float wq  = (float)(7 - (t >> 1));
        const bool updx = (t & 1) == 0;
        #pragma unroll
        for (int j = 0; j < 8; j++) {
            int o = rt * PLD + ct0 + j * 32;
            float4 g  = *(float4*)&sG[o];
            float4 fu = *(float4*)&sFu[o];
            float4 hv = *(float4*)&sHv[o];
            hv.x += 0.005f * (fu.x - g.x);
            hv.y += 0.005f * (fu.y - g.y);
            hv.z += 0.005f * (fu.z - g.z);
            hv.w += 0.005f * (fu.w - g.w);
            *(float4*)&sHv[o] = hv;
            float4 hx = *(float4*)&sHx[o];
            if (updx) {
                hx.x += 0.01f * hv.x; hx.y += 0.01f * hv.y;
                hx.z += 0.01f * hv.z; hx.w += 0.01f * hv.w;
                *(float4*)&sHx[o] = hx;
            }
            float4 p;
            p.x = tanh_fast(hx.x) * hv.x * hv.x;
            p.y = tanh_fast(hx.y) * hv.y * hv.y;
            p.z = tanh_fast(hx.z) * hv.z * hv.z;
            p.w = tanh_fast(hx.w) * hv.w * hv.w;
            *(__half2*)&sP[o]     = __floats2half2_rn(p.x, p.y);
            *(__half2*)&sP[o + 2] = __floats2half2_rn(p.z, p.w);
            Sv[j*4+0] += p.x; Sv[j*4+1] += p.y; Sv[j*4+2] += p.z; Sv[j*4+3] += p.w;
            Sx[j*4+0] += wq * p.x; Sx[j*4+1] += wq * p.y;
            Sx[j*4+2] += wq * p.z; Sx[j*4+3] += wq * p.w;
        }
        __syncthreads();
        if (t + 1 < 15) loadW(0, 0);
    }

    // ---- write sums as half ----
    #pragma unroll
    for (int j = 0; j < 8; j++) {
        size_t g = (size_t)(base + rt) * Rr + ct0 + j * 32;
        *(__half2*)(g_Svh + g)     = __floats2half2_rn(Sv[j*4+0], Sv[j*4+1]);
        *(__half2*)(g_Svh + g + 2) = __floats2half2_rn(Sv[j*4+2], Sv[j*4+3]);
        *(__half2*)(g_Sxh + g)     = __floats2half2_rn(Sx[j*4+0], Sx[j*4+1]);
        *(__half2*)(g_Sxh + g + 2) = __floats2half2_rn(Sx[j*4+2], Sx[j*4+3]);
    }
}

// ===========================================================================
// kFinal: dual fp16 GEMM (Sxh, Svh) @ Wh, fused output. Tile 128x64, BK=64,
// grid (16,32).
// ===========================================================================
constexpr int F_LDA = 72, F_LDB = 72, F_LDG = 68;
constexpr int F_STAGE_H = 2 * 128 * F_LDA + 64 * F_LDB;   // 23040 halves
constexpr int F_SMEM = 2 * F_STAGE_H * 2;                 // 92160 B (> 2*128*68*4)

__global__ void __launch_bounds__(256, 1)
kFinal(const float* __restrict__ x0, const float* __restrict__ v0,
       const float* __restrict__ Fin, float* __restrict__ Xw, float* __restrict__ Vw)
{
    extern __shared__ __half smh[];
    const int bn = blockIdx.x, bm = blockIdx.y;
    const int tid = threadIdx.x, warp = tid >> 5;
    const int wRow = (warp & 3) * 32, wCol = (warp >> 2) * 32;

    AccH acc[2][2][2];
    #pragma unroll
    for (int o = 0; o < 2; o++)
        #pragma unroll
        for (int i = 0; i < 2; i++)
            #pragma unroll
            for (int j = 0; j < 2; j++) wmma::fill_fragment(acc[o][i][j], 0.0f);

    const __half* Ag[2] = { g_Sxh + (size_t)bm * 128 * Rr,
                            g_Svh + (size_t)bm * 128 * Rr };
    const __half* Bg = g_Wh + bn * 64;

    auto load_stage = [&](int kt, int s) {
        __half* st = smh + s * F_STAGE_H;
        const int k0 = kt * 64;
        #pragma unroll
        for (int o = 0; o < 2; o++) {
            __half* sA = st + o * 128 * F_LDA;
            #pragma unroll
            for (int it = 0; it < 4; it++) {
                int u = tid + it * 256;
                int r = u >> 3, c8 = u & 7;
                cp_async16(&sA[r * F_LDA + c8 * 8], Ag[o] + (size_t)r * Rr + k0 + c8 * 8);
            }
        }
        __half* sB = st + 2 * 128 * F_LDA;
        #pragma unroll
        for (int it = 0; it < 2; it++) {
            int u = tid + it * 256;
            int r = u >> 3, c8 = u & 7;
            cp_async16(&sB[r * F_LDB + c8 * 8], Bg + (size_t)(k0 + r) * Dd + c8 * 8);
        }
        cp_commit();
    };

    constexpr int KT = Rr / 64;   // 4
    load_stage(0, 0);
    for (int kt = 0; kt < KT; kt++) {
        if (kt + 1 < KT) { load_stage(kt + 1, (kt + 1) & 1); cp_wait<1>(); }
        else             { cp_wait<0>(); }
        __syncthreads();
        const __half* st = smh + (kt & 1) * F_STAGE_H;
        const __half* sB = st + 2 * 128 * F_LDA;
        #pragma unroll
        for (int kk = 0; kk < 4; kk++) {
            AH af[2][2]; BH bf[2];
            #pragma unroll
            for (int o = 0; o < 2; o++)
                #pragma unroll
                for (int i = 0; i < 2; i++)
                    wmma::load_matrix_sync(af[o][i],
                        st + o * 128 * F_LDA + (wRow + i * 16) * F_LDA + kk * 16, F_LDA);
            #pragma unroll
            for (int j = 0; j < 2; j++)
                wmma::load_matrix_sync(bf[j], sB + (kk * 16) * F_LDB + wCol + j * 16, F_LDB);
            #pragma unroll
            for (int o = 0; o < 2; o++)
                #pragma unroll
                for (int i = 0; i < 2; i++)
                    #pragma unroll
                    for (int j = 0; j < 2; j++)
                        wmma::mma_sync(acc[o][i][j], af[o][i], bf[j], acc[o][i][j]);
        }
        __syncthreads();
    }

    float* sGx = (float*)smh;
    float* sGv = sGx + 128 * F_LDG;
    #pragma unroll
    for (int i = 0; i < 2; i++)
        #pragma unroll
        for (int j = 0; j < 2; j++) {
            wmma::store_matrix_sync(&sGx[(wRow + i * 16) * F_LDG + wCol + j * 16],
                                    acc[0][i][j], F_LDG, wmma::mem_row_major);
            wmma::store_matrix_sync(&sGv[(wRow + i * 16) * F_LDG + wCol + j * 16],
                                    acc[1][i][j], F_LDG, wmma::mem_row_major);
        }
    __syncthreads();

    const float c_xv = 0.08f;        // 8*dt
    const float c_xf = 0.0032f;      // 64*dt*hdt
    const float c_xg = 5e-5f;        // dt*hdt
    const float c_vf = 0.08f;        // 16*hdt
    const float c_vg = 0.005f;       // hdt
    #pragma unroll
    for (int it = 0; it < 8; it++) {
        int u = tid + it * 256;
        int r = u >> 4, c4 = u & 15;
        float4 gx = *(float4*)&sGx[r * F_LDG + c4 * 4];
        float4 gv = *(float4*)&sGv[r * F_LDG + c4 * 4];
        size_t idx = (size_t)(bm * 128 + r) * Dd + bn * 64 + c4 * 4;
        float4 x = *(const float4*)(x0 + idx);
        float4 v = *(const float4*)(v0 + idx);
        float4 f = *(const float4*)(Fin + idx);
        float4 xo, vo;
        xo.x = x.x + c_xv * v.x + c_xf * f.x - c_xg * gx.x;
        xo.y = x.y + c_xv * v.y + c_xf * f.y - c_xg * gx.y;
        xo.z = x.z + c_xv * v.z + c_xf * f.z - c_xg * gx.z;
        xo.w = x.w + c_xv * v.w + c_xf * f.w - c_xg * gx.w;
        vo.x = v.x + c_vf * f.x - c_vg * gv.x;
        vo.y = v.y + c_vf * f.y - c_vg * gv.y;
        vo.z = v.z + c_vf * f.z - c_vg * gv.z;
        vo.w = v.w + c_vf * f.w - c_vg * gv.w;
        *(float4*)(Xw + idx) = xo;
        *(float4*)(Vw + idx) = vo;
    }
}

// ===========================================================================
extern "C" void kernel_launch(void* const* d_in, const int* in_sizes, int n_in,
                              void* d_out, int out_size)
{
    const float* x0 = (const float*)d_in[0];
    const float* v0 = (const float*)d_in[1];
    const float* F  = (const float*)d_in[2];
    const float* U  = (const float*)d_in[3];
    const float* W  = (const float*)d_in[4];

    float* Xw = (float*)d_out;
    float* Vw = Xw + (size_t)Bsz * Dd;

    cudaFuncSetAttribute(kWU,    cudaFuncAttributeMaxDynamicSharedMemorySize, W_SMEM);
    cudaFuncSetAttribute(kInit,  cudaFuncAttributeMaxDynamicSharedMemorySize, I_SMEM);
    cudaFuncSetAttribute(kSteps, cudaFuncAttributeMaxDynamicSharedMemorySize, (int)PS_SMEM);
    cudaFuncSetAttribute(kFinal, cudaFuncAttributeMaxDynamicSharedMemorySize, F_SMEM);

    void *pXh, *pVh, *pFh, *pUh, *pWh;
    cudaGetSymbolAddress(&pXh, g_Xh);
    cudaGetSymbolAddress(&pVh, g_Vh);
    cudaGetSymbolAddress(&pFh, g_Fh);
    cudaGetSymbolAddress(&pUh, g_Uh);
    cudaGetSymbolAddress(&pWh, g_Wh);

    const int nBD4 = Bsz * Dd / 4;   // 1048576
    const int nDR4 = Dd * Rr / 4;    // 65536
    kCvt<<<nBD4 / 256, 256>>>((const float4*)x0, (__half2*)pXh, nBD4);
    kCvt<<<nBD4 / 256, 256>>>((const float4*)v0, (__half2*)pVh, nBD4);
    kCvt<<<nBD4 / 256, 256>>>((const float4*)F,  (__half2*)pFh, nBD4);
    kCvt<<<nDR4 / 256, 256>>>((const float4*)U,  (__half2*)pUh, nDR4);
    kCvt<<<nDR4 / 256, 256>>>((const float4*)W,  (__half2*)pWh, nDR4);

    dim3 blk(256);
    kWU<<<dim3(2, 2, 8), blk, W_SMEM>>>();
    kRed<<<Rr * Rr / 256, 256>>>();
    kInit<<<dim3(4, 32), blk, I_SMEM>>>();
    kSteps<<<128, blk, PS_SMEM>>>();
    kFinal<<<dim3(16, 32), blk, F_SMEM>>>(x0, v0, F, Xw, Vw);
}

// round 13
// speedup vs baseline: 4.7713x; 1.3171x over previous
#include <cuda_runtime.h>
#include <mma.h>
#include <cuda_fp16.h>
#include <math.h>

using namespace nvcuda;

#define Bsz 4096
#define Dd  1024
#define Rr  256

// ---------------- device scratch ----------------
static __device__ float  g_hx[(size_t)Bsz * Rr];
static __device__ float  g_hv[(size_t)Bsz * Rr];
static __device__ float  g_fU[(size_t)Bsz * Rr];
static __device__ float  g_P [(size_t)Bsz * Rr];
static __device__ float  g_WUp[(size_t)8 * Rr * Rr];
static __device__ __align__(16) __half g_Xh[(size_t)Bsz * Dd];
static __device__ __align__(16) __half g_Vh[(size_t)Bsz * Dd];
static __device__ __align__(16) __half g_Fh[(size_t)Bsz * Dd];
static __device__ __align__(16) __half g_Uh[(size_t)Dd * Rr];
static __device__ __align__(16) __half g_Wh[(size_t)Rr * Dd];
static __device__ __align__(16) __half g_WUh[(size_t)Rr * Rr];
static __device__ __align__(16) __half g_Svh[(size_t)Bsz * Rr];
static __device__ __align__(16) __half g_Sxh[(size_t)Bsz * Rr];

// ---------------- helpers ----------------
__device__ __forceinline__ void cp_async16(void* sptr, const void* gptr) {
    unsigned s = (unsigned)__cvta_generic_to_shared(sptr);
    asm volatile("cp.async.cg.shared.global [%0], [%1], 16;\n" :: "r"(s), "l"(gptr));
}
__device__ __forceinline__ void cp_commit() { asm volatile("cp.async.commit_group;\n"); }
template <int N> __device__ __forceinline__ void cp_wait() {
    asm volatile("cp.async.wait_group %0;\n" :: "n"(N));
}
__device__ __forceinline__ float tanh_fast(float x) {
    float y; asm("tanh.approx.f32 %0, %1;" : "=f"(y) : "f"(x)); return y;
}

typedef wmma::fragment<wmma::accumulator, 16, 16, 16, float>  AccH;
typedef wmma::fragment<wmma::accumulator, 16, 16, 16, __half> AccHF;
typedef wmma::fragment<wmma::matrix_a, 16, 16, 16, __half, wmma::row_major> AH;
typedef wmma::fragment<wmma::matrix_b, 16, 16, 16, __half, wmma::row_major> BH;

// ===========================================================================
// kCvt3: fp32 -> fp16 for X, V, F in one launch (blockIdx.y picks array)
// ===========================================================================
__global__ void kCvt3(const float4* __restrict__ i0, const float4* __restrict__ i1,
                      const float4* __restrict__ i2,
                      __half2* __restrict__ o0, __half2* __restrict__ o1,
                      __half2* __restrict__ o2)
{
    const float4* in  = (blockIdx.y == 0) ? i0 : (blockIdx.y == 1) ? i1 : i2;
    __half2*      out = (blockIdx.y == 0) ? o0 : (blockIdx.y == 1) ? o1 : o2;
    int i = blockIdx.x * 256 + threadIdx.x;
    float4 f = in[i];
    out[2 * i]     = __floats2half2_rn(f.x, f.y);
    out[2 * i + 1] = __floats2half2_rn(f.z, f.w);
}

__global__ void kCvt(const float4* __restrict__ in, __half2* __restrict__ out, int n4) {
    int i = blockIdx.x * 256 + threadIdx.x;
    if (i < n4) {
        float4 f = in[i];
        out[2 * i]     = __floats2half2_rn(f.x, f.y);
        out[2 * i + 1] = __floats2half2_rn(f.z, f.w);
    }
}

// ===========================================================================
// kWU: WU = Wh@Uh  [256,1024]@[1024,256], split-K (8 x 128). Grid (2,2,8).
// ===========================================================================
constexpr int W_LDA = 72;
constexpr int W_LDB = 136;
constexpr int W_STAGE_H = 128 * W_LDA + 64 * W_LDB;
constexpr int W_SMEM = 2 * W_STAGE_H * 2;

__global__ void __launch_bounds__(256, 1)
kWU()
{
    extern __shared__ __half smh[];
    const int bnn = blockIdx.x, bm = blockIdx.y, kz = blockIdx.z;
    const int tid = threadIdx.x, warp = tid >> 5;
    const int wRow = (warp & 3) * 32, wCol = (warp >> 2) * 64;

    AccH acc[2][4];
    #pragma unroll
    for (int i = 0; i < 2; i++)
        #pragma unroll
        for (int j = 0; j < 4; j++) wmma::fill_fragment(acc[i][j], 0.0f);

    const __half* Ag = g_Wh + (size_t)bm * 128 * Dd + kz * 128;
    const __half* Bg = g_Uh + (size_t)kz * 128 * Rr + bnn * 128;

    auto load_stage = [&](int kt, int s) {
        __half* sA = smh + s * W_STAGE_H;
        __half* sB = sA + 128 * W_LDA;
        const int k0 = kt * 64;
        #pragma unroll
        for (int it = 0; it < 4; it++) {
            int u = tid + it * 256;
            int r = u >> 3, c8 = u & 7;
            cp_async16(&sA[r * W_LDA + c8 * 8], Ag + (size_t)r * Dd + k0 + c8 * 8);
        }
        #pragma unroll
        for (int it = 0; it < 4; it++) {
            int u = tid + it * 256;
            int r = u >> 4, c8 = u & 15;
            cp_async16(&sB[r * W_LDB + c8 * 8], Bg + (size_t)(k0 + r) * Rr + c8 * 8);
        }
        cp_commit();
    };

    constexpr int KT = 2;
    load_stage(0, 0);
    for (int kt = 0; kt < KT; kt++) {
        if (kt + 1 < KT) { load_stage(kt + 1, (kt + 1) & 1); cp_wait<1>(); }
        else             { cp_wait<0>(); }
        __syncthreads();
        const __half* sA = smh + (kt & 1) * W_STAGE_H;
        const __half* sB = sA + 128 * W_LDA;
        #pragma unroll
        for (int kk = 0; kk < 4; kk++) {
            AH af[2]; BH bf[4];
            #pragma unroll
            for (int i = 0; i < 2; i++)
                wmma::load_matrix_sync(af[i], sA + (wRow + i * 16) * W_LDA + kk * 16, W_LDA);
            #pragma unroll
            for (int j = 0; j < 4; j++)
                wmma::load_matrix_sync(bf[j], sB + (kk * 16) * W_LDB + wCol + j * 16, W_LDB);
            #pragma unroll
            for (int i = 0; i < 2; i++)
                #pragma unroll
                for (int j = 0; j < 4; j++)
                    wmma::mma_sync(acc[i][j], af[i], bf[j], acc[i][j]);
        }
        __syncthreads();
    }

    float* out = g_WUp + (size_t)kz * Rr * Rr;
    #pragma unroll
    for (int i = 0; i < 2; i++)
        #pragma unroll
        for (int j = 0; j < 4; j++)
            wmma::store_matrix_sync(out + (size_t)(bm * 128 + wRow + i * 16) * Rr
                                        + bnn * 128 + wCol + j * 16,
                                    acc[i][j], Rr, wmma::mem_row_major);
}

__global__ void kRed() {
    int i = blockIdx.x * 256 + threadIdx.x;
    float s = 0.0f;
    #pragma unroll
    for (int z = 0; z < 8; z++) s += g_WUp[(size_t)z * Rr * Rr + i];
    g_WUh[i] = __float2half_rn(s);
}

// ===========================================================================
// kInit: hx = X@U, hv = V@U, fU = F@U. Tile 128x64, BK=64, grid (4,32).
// ===========================================================================
constexpr int I_LDA = 72;
constexpr int I_LDU = 72;
constexpr int I_STAGE_H = 3 * 128 * I_LDA + 64 * I_LDU;
constexpr int I_SMEM = 2 * I_STAGE_H * 2;

__global__ void __launch_bounds__(256, 1)
kInit()
{
    extern __shared__ __half smh[];
    const int bn = blockIdx.x, bm = blockIdx.y;
    const int tid = threadIdx.x, warp = tid >> 5;
    const int wRow = (warp & 3) * 32, wCol = (warp >> 2) * 32;

    AccH acc[3][2][2];
    #pragma unroll
    for (int o = 0; o < 3; o++)
        #pragma unroll
        for (int i = 0; i < 2; i++)
            #pragma unroll
            for (int j = 0; j < 2; j++) wmma::fill_fragment(acc[o][i][j], 0.0f);

    const __half* Ag[3] = { g_Xh + (size_t)bm * 128 * Dd,
                            g_Vh + (size_t)bm * 128 * Dd,
                            g_Fh + (size_t)bm * 128 * Dd };
    const __half* Ug = g_Uh + bn * 64;

    auto load_stage = [&](int kt, int s) {
        __half* st = smh + s * I_STAGE_H;
        const int k0 = kt * 64;
        #pragma unroll
        for (int o = 0; o < 3; o++) {
            __half* sA = st + o * 128 * I_LDA;
            #pragma unroll
            for (int it = 0; it < 4; it++) {
                int u = tid + it * 256;
                int r = u >> 3, c8 = u & 7;
                cp_async16(&sA[r * I_LDA + c8 * 8], Ag[o] + (size_t)r * Dd + k0 + c8 * 8);
            }
        }
        __half* sU = st + 3 * 128 * I_LDA;
        #pragma unroll
        for (int it = 0; it < 2; it++) {
            int u = tid + it * 256;
            int r = u >> 3, c8 = u & 7;
            cp_async16(&sU[r * I_LDU + c8 * 8], Ug + (size_t)(k0 + r) * Rr + c8 * 8);
        }
        cp_commit();
    };

    constexpr int KT = Dd / 64;
    load_stage(0, 0);
    for (int kt = 0; kt < KT; kt++) {
        if (kt + 1 < KT) { load_stage(kt + 1, (kt + 1) & 1); cp_wait<1>(); }
        else             { cp_wait<0>(); }
        __syncthreads();
        const __half* st = smh + (kt & 1) * I_STAGE_H;
        const __half* sU = st + 3 * 128 * I_LDA;
        #pragma unroll
        for (int kk = 0; kk < 4; kk++) {
            AH af[3][2]; BH bu[2];
            #pragma unroll
            for (int o = 0; o < 3; o++)
                #pragma unroll
                for (int i = 0; i < 2; i++)
                    wmma::load_matrix_sync(af[o][i],
                        st + o * 128 * I_LDA + (wRow + i * 16) * I_LDA + kk * 16, I_LDA);
            #pragma unroll
            for (int j = 0; j < 2; j++)
                wmma::load_matrix_sync(bu[j], sU + (kk * 16) * I_LDU + wCol + j * 16, I_LDU);
            #pragma unroll
            for (int o = 0; o < 3; o++)
                #pragma unroll
                for (int i = 0; i < 2; i++)
                    #pragma unroll
                    for (int j = 0; j < 2; j++)
                        wmma::mma_sync(acc[o][i][j], af[o][i], bu[j], acc[o][i][j]);
        }
        __syncthreads();
    }

    #pragma unroll
    for (int i = 0; i < 2; i++)
        #pragma unroll
        for (int j = 0; j < 2; j++) {
            size_t off = (size_t)(bm * 128 + wRow + i * 16) * Rr + bn * 64 + wCol + j * 16;
            wmma::store_matrix_sync(g_hx + off, acc[0][i][j], Rr, wmma::mem_row_major);
            wmma::store_matrix_sync(g_hv + off, acc[1][i][j], Rr, wmma::mem_row_major);
            wmma::store_matrix_sync(g_fU + off, acc[2][i][j], Rr, wmma::mem_row_major);
            #pragma unroll
            for (int e = 0; e < acc[0][i][j].num_elements; e++) {
                float h = acc[1][i][j].x[e];
                acc[0][i][j].x[e] = tanh_fast(acc[0][i][j].x[e]) * h * h;
            }
            wmma::store_matrix_sync(g_P + off, acc[0][i][j], Rr, wmma::mem_row_major);
        }
}

// ===========================================================================
// kSteps: persistent, all 15 half-steps. 128 CTAs x 256 thr; CTA owns 32 rows.
// WU (half) FULLY smem-resident (loaded once). hx/hv fp32 smem (unpadded),
// P half smem (padded for wmma), fU in registers. gamma computed with fp16
// accumulators, stored in-place over sP. 3 syncthreads per step, zero global
// traffic in the loop.
// ===========================================================================
constexpr int PLD = 264;   // half stride for wmma-accessed tiles (mult of 8)
constexpr size_t PSB_WU = 0;                               // 256*264*2 = 135168
constexpr size_t PSB_HV = PSB_WU + 256 * PLD * 2;          // fp32 32*256*4 = 32768
constexpr size_t PSB_HX = PSB_HV + 32 * 256 * 4;           // fp32 32768
constexpr size_t PSB_P  = PSB_HX + 32 * 256 * 4;           // half 32*264*2 = 16896
constexpr size_t PS_SMEM = PSB_P + 32 * PLD * 2;           // 217600 B

__global__ void __launch_bounds__(256, 1)
kSteps()
{
    extern __shared__ char smc[];
    __half* sWU = (__half*)(smc + PSB_WU);
    float*  sHv = (float*)(smc + PSB_HV);
    float*  sHx = (float*)(smc + PSB_HX);
    __half* sP  = (__half*)(smc + PSB_P);

    const int tid  = threadIdx.x;
    const int warp = tid >> 5;
    const int wm = warp & 1, wn = warp >> 1;   // 2 warps M x 4 warps N
    const int base = blockIdx.x * 32;

    // ---- load WU (once): 256x256 halves ----
    #pragma unroll
    for (int it = 0; it < 32; it++) {
        int u = tid + it * 256;
        int r = u >> 5, c8 = u & 31;
        cp_async16(&sWU[r * PLD + c8 * 8], g_WUh + (size_t)r * Rr + c8 * 8);
    }
    cp_commit();

    // ---- load state ----
    #pragma unroll
    for (int it = 0; it < 8; it++) {
        int u = tid + it * 256;
        int r = u >> 6, c = (u & 63) * 4;
        size_t g = (size_t)(base + r) * Rr + c;
        *(float4*)&sHv[r * 256 + c] = *(const float4*)(g_hv + g);
        *(float4*)&sHx[r * 256 + c] = *(const float4*)(g_hx + g);
        float4 p = *(const float4*)(g_P + g);
        *(__half2*)&sP[r * PLD + c]     = __floats2half2_rn(p.x, p.y);
        *(__half2*)&sP[r * PLD + c + 2] = __floats2half2_rn(p.z, p.w);
    }

    // ---- fU in registers (thread owns rows rt, cols ct0 + j*32 .. +3) ----
    const int rt  = tid >> 3;
    const int ct0 = (tid & 7) * 4;
    float fu[32];
    #pragma unroll
    for (int j = 0; j < 8; j++) {
        float4 f = *(const float4*)(g_fU + (size_t)(base + rt) * Rr + ct0 + j * 32);
        fu[j*4+0] = f.x; fu[j*4+1] = f.y; fu[j*4+2] = f.z; fu[j*4+3] = f.w;
    }

    cp_wait<0>();
    __syncthreads();

    // ---- register sums, init from P0 (Sv=P0, Sx=8*P0) ----
    float Sv[32], Sx[32];
    #pragma unroll
    for (int j = 0; j < 8; j++) {
        int o = rt * PLD + ct0 + j * 32;
        #pragma unroll
        for (int q = 0; q < 4; q++) {
            float p = __half2float(sP[o + q]);
            Sv[j*4+q] = p; Sx[j*4+q] = 8.0f * p;
        }
    }

    #pragma unroll 1
    for (int t = 0; t < 15; t++) {
        // ---- GEMM: gamma[32,256] = P[32,256] @ WU[256,256], fp16 acc ----
        AccHF acc[4];
        #pragma unroll
        for (int j = 0; j < 4; j++) wmma::fill_fragment(acc[j], (__half)0.0f);

        #pragma unroll
        for (int k = 0; k < 16; k++) {
            AH a;
            wmma::load_matrix_sync(a, &sP[(wm * 16) * PLD + k * 16], PLD);
            #pragma unroll
            for (int j = 0; j < 4; j++) {
                BH bf;
                wmma::load_matrix_sync(bf, &sWU[(k * 16) * PLD + wn * 64 + j * 16], PLD);
                wmma::mma_sync(acc[j], a, bf, acc[j]);
            }
        }
        __syncthreads();   // all warps finished reading sP

        // ---- store gamma (half) in place over sP ----
        #pragma unroll
        for (int j = 0; j < 4; j++)
            wmma::store_matrix_sync(&sP[(wm * 16) * PLD + wn * 64 + j * 16],
                                    acc[j], PLD, wmma::mem_row_major);
        __syncthreads();

        // ---- fused elementwise half-step (reads gamma from sP, writes P back) ----
        const float wq  = (float)(7 - (t >> 1));
        const bool updx = (t & 1) == 0;
        #pragma unroll
        for (int j = 0; j < 8; j++) {
            int oh = rt * PLD + ct0 + j * 32;
            int of = rt * 256 + ct0 + j * 32;
            float2 g0 = __half22float2(*(__half2*)&sP[oh]);
            float2 g1 = __half22float2(*(__half2*)&sP[oh + 2]);
            float4 hv = *(float4*)&sHv[of];
            hv.x += 0.005f * (fu[j*4+0] - g0.x);
            hv.y += 0.005f * (fu[j*4+1] - g0.y);
            hv.z += 0.005f * (fu[j*4+2] - g1.x);
            hv.w += 0.005f * (fu[j*4+3] - g1.y);
            *(float4*)&sHv[of] = hv;
            float4 hx = *(float4*)&sHx[of];
            if (updx) {
                hx.x += 0.01f * hv.x; hx.y += 0.01f * hv.y;
                hx.z += 0.01f * hv.z; hx.w += 0.01f * hv.w;
                *(float4*)&sHx[of] = hx;
            }
            float4 p;
            p.x = tanh_fast(hx.x) * hv.x * hv.x;
            p.y = tanh_fast(hx.y) * hv.y * hv.y;
            p.z = tanh_fast(hx.z) * hv.z * hv.z;
            p.w = tanh_fast(hx.w) * hv.w * hv.w;
            *(__half2*)&sP[oh]     = __floats2half2_rn(p.x, p.y);
            *(__half2*)&sP[oh + 2] = __floats2half2_rn(p.z, p.w);
            Sv[j*4+0] += p.x; Sv[j*4+1] += p.y; Sv[j*4+2] += p.z; Sv[j*4+3] += p.w;
            Sx[j*4+0] += wq * p.x; Sx[j*4+1] += wq * p.y;
            Sx[j*4+2] += wq * p.z; Sx[j*4+3] += wq * p.w;
        }
        __syncthreads();
    }

    // ---- write sums as half ----
    #pragma unroll
    for (int j = 0; j < 8; j++) {
        size_t g = (size_t)(base + rt) * Rr + ct0 + j * 32;
        *(__half2*)(g_Svh + g)     = __floats2half2_rn(Sv[j*4+0], Sv[j*4+1]);
        *(__half2*)(g_Svh + g + 2) = __floats2half2_rn(Sv[j*4+2], Sv[j*4+3]);
        *(__half2*)(g_Sxh + g)     = __floats2half2_rn(Sx[j*4+0], Sx[j*4+1]);
        *(__half2*)(g_Sxh + g + 2) = __floats2half2_rn(Sx[j*4+2], Sx[j*4+3]);
    }
}

// ===========================================================================
// kFinal: dual fp16 GEMM (Sxh, Svh) @ Wh with fp16 accumulators, fused output.
// Tile 128x64, BK=64, grid (16,32), occupancy 2.
// ===========================================================================
constexpr int F_LDA = 72, F_LDB = 72, F_LDG = 72;
constexpr int F_STAGE_H = 2 * 128 * F_LDA + 64 * F_LDB;   // 23040 halves
constexpr int F_SMEM = 2 * F_STAGE_H * 2;                 // 92160 B

__global__ void __launch_bounds__(256, 2)
kFinal(const float* __restrict__ x0, const float* __restrict__ v0,
       const float* __restrict__ Fin, float* __restrict__ Xw, float* __restrict__ Vw)
{
    extern __shared__ __half smh[];
    const int bn = blockIdx.x, bm = blockIdx.y;
    const int tid = threadIdx.x, warp = tid >> 5;
    const int wRow = (warp & 3) * 32, wCol = (warp >> 2) * 32;

    AccHF acc[2][2][2];
    #pragma unroll
    for (int o = 0; o < 2; o++)
        #pragma unroll
        for (int i = 0; i < 2; i++)
            #pragma unroll
            for (int j = 0; j < 2; j++) wmma::fill_fragment(acc[o][i][j], (__half)0.0f);

    const __half* Ag[2] = { g_Sxh + (size_t)bm * 128 * Rr,
                            g_Svh + (size_t)bm * 128 * Rr };
    const __half* Bg = g_Wh + bn * 64;

    auto load_stage = [&](int kt, int s) {
        __half* st = smh + s * F_STAGE_H;
        const int k0 = kt * 64;
        #pragma unroll
        for (int o = 0; o < 2; o++) {
            __half* sA = st + o * 128 * F_LDA;
            #pragma unroll
            for (int it = 0; it < 4; it++) {
                int u = tid + it * 256;
                int r = u >> 3, c8 = u & 7;
                cp_async16(&sA[r * F_LDA + c8 * 8], Ag[o] + (size_t)r * Rr + k0 + c8 * 8);
            }
        }
        __half* sB = st + 2 * 128 * F_LDA;
        #pragma unroll
        for (int it = 0; it < 2; it++) {
            int u = tid + it * 256;
            int r = u >> 3, c8 = u & 7;
            cp_async16(&sB[r * F_LDB + c8 * 8], Bg + (size_t)(k0 + r) * Dd + c8 * 8);
        }
        cp_commit();
    };

    constexpr int KT = Rr / 64;   // 4
    load_stage(0, 0);
    for (int kt = 0; kt < KT; kt++) {
        if (kt + 1 < KT) { load_stage(kt + 1, (kt + 1) & 1); cp_wait<1>(); }
        else             { cp_wait<0>(); }
        __syncthreads();
        const __half* st = smh + (kt & 1) * F_STAGE_H;
        const __half* sB = st + 2 * 128 * F_LDA;
        #pragma unroll
        for (int kk = 0; kk < 4; kk++) {
            AH af[2][2]; BH bf[2];
            #pragma unroll
            for (int o = 0; o < 2; o++)
                #pragma unroll
                for (int i = 0; i < 2; i++)
                    wmma::load_matrix_sync(af[o][i],
                        st + o * 128 * F_LDA + (wRow + i * 16) * F_LDA + kk * 16, F_LDA);
            #pragma unroll
            for (int j = 0; j < 2; j++)
                wmma::load_matrix_sync(bf[j], sB + (kk * 16) * F_LDB + wCol + j * 16, F_LDB);
            #pragma unroll
            for (int o = 0; o < 2; o++)
                #pragma unroll
                for (int i = 0; i < 2; i++)
                    #pragma unroll
                    for (int j = 0; j < 2; j++)
                        wmma::mma_sync(acc[o][i][j], af[o][i], bf[j], acc[o][i][j]);
        }
        __syncthreads();
    }

    __half* sGx = smh;                       // 128 x F_LDG halves
    __half* sGv = smh + 128 * F_LDG;
    #pragma unroll
    for (int i = 0; i < 2; i++)
        #pragma unroll
        for (int j = 0; j < 2; j++) {
            wmma::store_matrix_sync(&sGx[(wRow + i * 16) * F_LDG + wCol + j * 16],
                                    acc[0][i][j], F_LDG, wmma::mem_row_major);
            wmma::store_matrix_sync(&sGv[(wRow + i * 16) * F_LDG + wCol + j * 16],
                                    acc[1][i][j], F_LDG, wmma::mem_row_major);
        }
    __syncthreads();

    const float c_xv = 0.08f;        // 8*dt
    const float c_xf = 0.0032f;      // 64*dt*hdt
    const float c_xg = 5e-5f;        // dt*hdt
    const float c_vf = 0.08f;        // 16*hdt
    const float c_vg = 0.005f;       // hdt
    #pragma unroll
    for (int it = 0; it < 8; it++) {
        int u = tid + it * 256;
        int r = u >> 4, c4 = u & 15;
        float2 gx0 = __half22float2(*(__half2*)&sGx[r * F_LDG + c4 * 4]);
        float2 gx1 = __half22float2(*(__half2*)&sGx[r * F_LDG + c4 * 4 + 2]);
        float2 gv0 = __half22float2(*(__half2*)&sGv[r * F_LDG + c4 * 4]);
        float2 gv1 = __half22float2(*(__half2*)&sGv[r * F_LDG + c4 * 4 + 2]);
        size_t idx = (size_t)(bm * 128 + r) * Dd + bn * 64 + c4 * 4;
        float4 x = *(const float4*)(x0 + idx);
        float4 v = *(const float4*)(v0 + idx);
        float4 f = *(const float4*)(Fin + idx);
        float4 xo, vo;
        xo.x = x.x + c_xv * v.x + c_xf * f.x - c_xg * gx0.x;
        xo.y = x.y + c_xv * v.y + c_xf * f.y - c_xg * gx0.y;
        xo.z = x.z + c_xv * v.z + c_xf * f.z - c_xg * gx1.x;
        xo.w = x.w + c_xv * v.w + c_xf * f.w - c_xg * gx1.y;
        vo.x = v.x + c_vf * f.x - c_vg * gv0.x;
        vo.y = v.y + c_vf * f.y - c_vg * gv0.y;
        vo.z = v.z + c_vf * f.z - c_vg * gv1.x;
        vo.w = v.w + c_vf * f.w - c_vg * gv1.y;
        *(float4*)(Xw + idx) = xo;
        *(float4*)(Vw + idx) = vo;
    }
}

// ===========================================================================
extern "C" void kernel_launch(void* const* d_in, const int* in_sizes, int n_in,
                              void* d_out, int out_size)
{
    const float* x0 = (const float*)d_in[0];
    const float* v0 = (const float*)d_in[1];
    const float* F  = (const float*)d_in[2];
    const float* U  = (const float*)d_in[3];
    const float* W  = (const float*)d_in[4];

    float* Xw = (float*)d_out;
    float* Vw = Xw + (size_t)Bsz * Dd;

    cudaFuncSetAttribute(kWU,    cudaFuncAttributeMaxDynamicSharedMemorySize, W_SMEM);
    cudaFuncSetAttribute(kInit,  cudaFuncAttributeMaxDynamicSharedMemorySize, I_SMEM);
    cudaFuncSetAttribute(kSteps, cudaFuncAttributeMaxDynamicSharedMemorySize, (int)PS_SMEM);
    cudaFuncSetAttribute(kFinal, cudaFuncAttributeMaxDynamicSharedMemorySize, F_SMEM);

    void *pXh, *pVh, *pFh, *pUh, *pWh;
    cudaGetSymbolAddress(&pXh, g_Xh);
    cudaGetSymbolAddress(&pVh, g_Vh);
    cudaGetSymbolAddress(&pFh, g_Fh);
    cudaGetSymbolAddress(&pUh, g_Uh);
    cudaGetSymbolAddress(&pWh, g_Wh);

    const int nBD4 = Bsz * Dd / 4;
    const int nDR4 = Dd * Rr / 4;
    kCvt<<<nDR4 / 256, 256>>>((const float4*)U, (__half2*)pUh, nDR4);
    kCvt<<<nDR4 / 256, 256>>>((const float4*)W, (__half2*)pWh, nDR4);

    dim3 blk(256);
    kWU<<<dim3(2, 2, 8), blk, W_SMEM>>>();
    kRed<<<Rr * Rr / 256, 256>>>();

    kCvt3<<<dim3(nBD4 / 256, 3), 256>>>((const float4*)x0, (const float4*)v0,
                                        (const float4*)F,
                                        (__half2*)pXh, (__half2*)pVh, (__half2*)pFh);

    kInit<<<dim3(4, 32), blk, I_SMEM>>>();
    kSteps<<<128, blk, PS_SMEM>>>();
    kFinal<<<dim3(16, 32), blk, F_SMEM>>>(x0, v0, F, Xw, Vw);
}

// round 14
// speedup vs baseline: 4.7726x; 1.0003x over previous
#include <cuda_runtime.h>
#include <mma.h>
#include <cuda_fp16.h>
#include <math.h>

using namespace nvcuda;

#define Bsz 4096
#define Dd  1024
#define Rr  256

// ---------------- device scratch ----------------
static __device__ float  g_hx[(size_t)Bsz * Rr];
static __device__ float  g_hv[(size_t)Bsz * Rr];
static __device__ float  g_fU[(size_t)Bsz * Rr];
static __device__ float  g_P [(size_t)Bsz * Rr];
static __device__ float  g_WUp[(size_t)8 * Rr * Rr];
static __device__ __align__(16) __half g_Xh[(size_t)Bsz * Dd];
static __device__ __align__(16) __half g_Vh[(size_t)Bsz * Dd];
static __device__ __align__(16) __half g_Fh[(size_t)Bsz * Dd];
static __device__ __align__(16) __half g_Uh[(size_t)Dd * Rr];
static __device__ __align__(16) __half g_Wh[(size_t)Rr * Dd];
static __device__ __align__(16) __half g_WUh[(size_t)Rr * Rr];
static __device__ __align__(16) __half g_Svh[(size_t)Bsz * Rr];
static __device__ __align__(16) __half g_Sxh[(size_t)Bsz * Rr];

// ---------------- helpers ----------------
__device__ __forceinline__ void cp_async16(void* sptr, const void* gptr) {
    unsigned s = (unsigned)__cvta_generic_to_shared(sptr);
    asm volatile("cp.async.cg.shared.global [%0], [%1], 16;\n" :: "r"(s), "l"(gptr));
}
__device__ __forceinline__ void cp_commit() { asm volatile("cp.async.commit_group;\n"); }
template <int N> __device__ __forceinline__ void cp_wait() {
    asm volatile("cp.async.wait_group %0;\n" :: "n"(N));
}
__device__ __forceinline__ float tanh_fast(float x) {
    float y; asm("tanh.approx.f32 %0, %1;" : "=f"(y) : "f"(x)); return y;
}

typedef wmma::fragment<wmma::accumulator, 16, 16, 16, float>  AccH;
typedef wmma::fragment<wmma::accumulator, 16, 16, 16, __half> AccHF;
typedef wmma::fragment<wmma::matrix_a, 16, 16, 16, __half, wmma::row_major> AH;
typedef wmma::fragment<wmma::matrix_b, 16, 16, 16, __half, wmma::row_major> BH;

// ===========================================================================
// kCvt3: fp32 -> fp16 for X, V, F in one launch (blockIdx.y picks array)
// ===========================================================================
__global__ void kCvt3(const float4* __restrict__ i0, const float4* __restrict__ i1,
                      const float4* __restrict__ i2,
                      __half2* __restrict__ o0, __half2* __restrict__ o1,
                      __half2* __restrict__ o2)
{
    const float4* in  = (blockIdx.y == 0) ? i0 : (blockIdx.y == 1) ? i1 : i2;
    __half2*      out = (blockIdx.y == 0) ? o0 : (blockIdx.y == 1) ? o1 : o2;
    int i = blockIdx.x * 256 + threadIdx.x;
    float4 f = in[i];
    out[2 * i]     = __floats2half2_rn(f.x, f.y);
    out[2 * i + 1] = __floats2half2_rn(f.z, f.w);
}

// kCvt2: U and W in one launch
__global__ void kCvt2(const float4* __restrict__ i0, const float4* __restrict__ i1,
                      __half2* __restrict__ o0, __half2* __restrict__ o1)
{
    const float4* in  = (blockIdx.y == 0) ? i0 : i1;
    __half2*      out = (blockIdx.y == 0) ? o0 : o1;
    int i = blockIdx.x * 256 + threadIdx.x;
    float4 f = in[i];
    out[2 * i]     = __floats2half2_rn(f.x, f.y);
    out[2 * i + 1] = __floats2half2_rn(f.z, f.w);
}

// ===========================================================================
// kWU: WU = Wh@Uh  [256,1024]@[1024,256], split-K (8 x 128). Grid (2,2,8).
// ===========================================================================
constexpr int W_LDA = 72;
constexpr int W_LDB = 136;
constexpr int W_STAGE_H = 128 * W_LDA + 64 * W_LDB;
constexpr int W_SMEM = 2 * W_STAGE_H * 2;

__global__ void __launch_bounds__(256, 1)
kWU()
{
    extern __shared__ __half smh[];
    const int bnn = blockIdx.x, bm = blockIdx.y, kz = blockIdx.z;
    const int tid = threadIdx.x, warp = tid >> 5;
    const int wRow = (warp & 3) * 32, wCol = (warp >> 2) * 64;

    AccH acc[2][4];
    #pragma unroll
    for (int i = 0; i < 2; i++)
        #pragma unroll
        for (int j = 0; j < 4; j++) wmma::fill_fragment(acc[i][j], 0.0f);

    const __half* Ag = g_Wh + (size_t)bm * 128 * Dd + kz * 128;
    const __half* Bg = g_Uh + (size_t)kz * 128 * Rr + bnn * 128;

    auto load_stage = [&](int kt, int s) {
        __half* sA = smh + s * W_STAGE_H;
        __half* sB = sA + 128 * W_LDA;
        const int k0 = kt * 64;
        #pragma unroll
        for (int it = 0; it < 4; it++) {
            int u = tid + it * 256;
            int r = u >> 3, c8 = u & 7;
            cp_async16(&sA[r * W_LDA + c8 * 8], Ag + (size_t)r * Dd + k0 + c8 * 8);
        }
        #pragma unroll
        for (int it = 0; it < 4; it++) {
            int u = tid + it * 256;
            int r = u >> 4, c8 = u & 15;
            cp_async16(&sB[r * W_LDB + c8 * 8], Bg + (size_t)(k0 + r) * Rr + c8 * 8);
        }
        cp_commit();
    };

    constexpr int KT = 2;
    load_stage(0, 0);
    for (int kt = 0; kt < KT; kt++) {
        if (kt + 1 < KT) { load_stage(kt + 1, (kt + 1) & 1); cp_wait<1>(); }
        else             { cp_wait<0>(); }
        __syncthreads();
        const __half* sA = smh + (kt & 1) * W_STAGE_H;
        const __half* sB = sA + 128 * W_LDA;
        #pragma unroll
        for (int kk = 0; kk < 4; kk++) {
            AH af[2]; BH bf[4];
            #pragma unroll
            for (int i = 0; i < 2; i++)
                wmma::load_matrix_sync(af[i], sA + (wRow + i * 16) * W_LDA + kk * 16, W_LDA);
            #pragma unroll
            for (int j = 0; j < 4; j++)
                wmma::load_matrix_sync(bf[j], sB + (kk * 16) * W_LDB + wCol + j * 16, W_LDB);
            #pragma unroll
            for (int i = 0; i < 2; i++)
                #pragma unroll
                for (int j = 0; j < 4; j++)
                    wmma::mma_sync(acc[i][j], af[i], bf[j], acc[i][j]);
        }
        __syncthreads();
    }

    float* out = g_WUp + (size_t)kz * Rr * Rr;
    #pragma unroll
    for (int i = 0; i < 2; i++)
        #pragma unroll
        for (int j = 0; j < 4; j++)
            wmma::store_matrix_sync(out + (size_t)(bm * 128 + wRow + i * 16) * Rr
                                        + bnn * 128 + wCol + j * 16,
                                    acc[i][j], Rr, wmma::mem_row_major);
}

__global__ void kRed() {
    int i = blockIdx.x * 256 + threadIdx.x;
    float s = 0.0f;
    #pragma unroll
    for (int z = 0; z < 8; z++) s += g_WUp[(size_t)z * Rr * Rr + i];
    g_WUh[i] = __float2half_rn(s);
}

// ===========================================================================
// kInit: hx = X@U, hv = V@U, fU = F@U. Tile 64x64, BK=64, grid (4,64),
// occupancy 2 (256 CTAs = one full wave at 2/SM).
// ===========================================================================
constexpr int I_LDA = 72;
constexpr int I_LDU = 72;
constexpr int I_STAGE_H = 3 * 64 * I_LDA + 64 * I_LDU;   // 18432 halves
constexpr int I_SMEM = 2 * I_STAGE_H * 2;                // 73728 B

__global__ void __launch_bounds__(256, 2)
kInit()
{
    extern __shared__ __half smh[];
    const int bn = blockIdx.x, bm = blockIdx.y;
    const int tid = threadIdx.x, warp = tid >> 5;
    const int wm = warp & 1, wn = warp >> 1;   // 2 warps in M (32 rows), 4 in N (16 cols)
    const int wRow = wm * 32, wCol = wn * 16;

    AccH acc[3][2];
    #pragma unroll
    for (int o = 0; o < 3; o++)
        #pragma unroll
        for (int i = 0; i < 2; i++) wmma::fill_fragment(acc[o][i], 0.0f);

    const __half* Ag[3] = { g_Xh + (size_t)bm * 64 * Dd,
                            g_Vh + (size_t)bm * 64 * Dd,
                            g_Fh + (size_t)bm * 64 * Dd };
    const __half* Ug = g_Uh + bn * 64;

    auto load_stage = [&](int kt, int s) {
        __half* st = smh + s * I_STAGE_H;
        const int k0 = kt * 64;
        #pragma unroll
        for (int o = 0; o < 3; o++) {
            __half* sA = st + o * 64 * I_LDA;
            #pragma unroll
            for (int it = 0; it < 2; it++) {           // 64 rows x 8 c8 = 512
                int u = tid + it * 256;
                int r = u >> 3, c8 = u & 7;
                cp_async16(&sA[r * I_LDA + c8 * 8], Ag[o] + (size_t)r * Dd + k0 + c8 * 8);
            }
        }
        __half* sU = st + 3 * 64 * I_LDA;
        #pragma unroll
        for (int it = 0; it < 2; it++) {               // 64 rows x 8 c8 = 512
            int u = tid + it * 256;
            int r = u >> 3, c8 = u & 7;
            cp_async16(&sU[r * I_LDU + c8 * 8], Ug + (size_t)(k0 + r) * Rr + c8 * 8);
        }
        cp_commit();
    };

    constexpr int KT = Dd / 64;   // 16
    load_stage(0, 0);
    for (int kt = 0; kt < KT; kt++) {
        if (kt + 1 < KT) { load_stage(kt + 1, (kt + 1) & 1); cp_wait<1>(); }
        else             { cp_wait<0>(); }
        __syncthreads();
        const __half* st = smh + (kt & 1) * I_STAGE_H;
        const __half* sU = st + 3 * 64 * I_LDA;
        #pragma unroll
        for (int kk = 0; kk < 4; kk++) {
            BH bu;
            wmma::load_matrix_sync(bu, sU + (kk * 16) * I_LDU + wCol, I_LDU);
            #pragma unroll
            for (int o = 0; o < 3; o++) {
                #pragma unroll
                for (int i = 0; i < 2; i++) {
                    AH af;
                    wmma::load_matrix_sync(af,
                        st + o * 64 * I_LDA + (wRow + i * 16) * I_LDA + kk * 16, I_LDA);
                    wmma::mma_sync(acc[o][i], af, bu, acc[o][i]);
                }
            }
        }
        __syncthreads();
    }

    #pragma unroll
    for (int i = 0; i < 2; i++) {
        size_t off = (size_t)(bm * 64 + wRow + i * 16) * Rr + bn * 64 + wCol;
        wmma::store_matrix_sync(g_hx + off, acc[0][i], Rr, wmma::mem_row_major);
        wmma::store_matrix_sync(g_hv + off, acc[1][i], Rr, wmma::mem_row_major);
        wmma::store_matrix_sync(g_fU + off, acc[2][i], Rr, wmma::mem_row_major);
        #pragma unroll
        for (int e = 0; e < acc[0][i].num_elements; e++) {
            float h = acc[1][i].x[e];
            acc[0][i].x[e] = tanh_fast(acc[0][i].x[e]) * h * h;
        }
        wmma::store_matrix_sync(g_P + off, acc[0][i], Rr, wmma::mem_row_major);
    }
}

// ===========================================================================
// kSteps: persistent, all 15 half-steps. 128 CTAs x 256 thr; CTA owns 32 rows.
// WU fully smem-resident; hx/hv fp32 smem; P half smem; fU regs; fp16-acc GEMM.
// ===========================================================================
constexpr int PLD = 264;
constexpr size_t PSB_WU = 0;
constexpr size_t PSB_HV = PSB_WU + 256 * PLD * 2;
constexpr size_t PSB_HX = PSB_HV + 32 * 256 * 4;
constexpr size_t PSB_P  = PSB_HX + 32 * 256 * 4;
constexpr size_t PS_SMEM = PSB_P + 32 * PLD * 2;   // 217600 B

__global__ void __launch_bounds__(256, 1)
kSteps()
{
    extern __shared__ char smc[];
    __half* sWU = (__half*)(smc + PSB_WU);
    float*  sHv = (float*)(smc + PSB_HV);
    float*  sHx = (float*)(smc + PSB_HX);
    __half* sP  = (__half*)(smc + PSB_P);

    const int tid  = threadIdx.x;
    const int warp = tid >> 5;
    const int wm = warp & 1, wn = warp >> 1;
    const int base = blockIdx.x * 32;

    #pragma unroll
    for (int it = 0; it < 32; it++) {
        int u = tid + it * 256;
        int r = u >> 5, c8 = u & 31;
        cp_async16(&sWU[r * PLD + c8 * 8], g_WUh + (size_t)r * Rr + c8 * 8);
    }
    cp_commit();

    #pragma unroll
    for (int it = 0; it < 8; it++) {
        int u = tid + it * 256;
        int r = u >> 6, c = (u & 63) * 4;
        size_t g = (size_t)(base + r) * Rr + c;
        *(float4*)&sHv[r * 256 + c] = *(const float4*)(g_hv + g);
        *(float4*)&sHx[r * 256 + c] = *(const float4*)(g_hx + g);
        float4 p = *(const float4*)(g_P + g);
        *(__half2*)&sP[r * PLD + c]     = __floats2half2_rn(p.x, p.y);
        *(__half2*)&sP[r * PLD + c + 2] = __floats2half2_rn(p.z, p.w);
    }

    const int rt  = tid >> 3;
    const int ct0 = (tid & 7) * 4;
    float fu[32];
    #pragma unroll
    for (int j = 0; j < 8; j++) {
        float4 f = *(const float4*)(g_fU + (size_t)(base + rt) * Rr + ct0 + j * 32);
        fu[j*4+0] = f.x; fu[j*4+1] = f.y; fu[j*4+2] = f.z; fu[j*4+3] = f.w;
    }

    cp_wait<0>();
    __syncthreads();

    float Sv[32], Sx[32];
    #pragma unroll
    for (int j = 0; j < 8; j++) {
        int o = rt * PLD + ct0 + j * 32;
        #pragma unroll
        for (int q = 0; q < 4; q++) {
            float p = __half2float(sP[o + q]);
            Sv[j*4+q] = p; Sx[j*4+q] = 8.0f * p;
        }
    }

    #pragma unroll 1
    for (int t = 0; t < 15; t++) {
        AccHF acc[4];
        #pragma unroll
        for (int j = 0; j < 4; j++) wmma::fill_fragment(acc[j], (__half)0.0f);

        #pragma unroll
        for (int k = 0; k < 16; k++) {
            AH a;
            wmma::load_matrix_sync(a, &sP[(wm * 16) * PLD + k * 16], PLD);
            #pragma unroll
            for (int j = 0; j < 4; j++) {
                BH bf;
                wmma::load_matrix_sync(bf, &sWU[(k * 16) * PLD + wn * 64 + j * 16], PLD);
                wmma::mma_sync(acc[j], a, bf, acc[j]);
            }
        }
        __syncthreads();

        #pragma unroll
        for (int j = 0; j < 4; j++)
            wmma::store_matrix_sync(&sP[(wm * 16) * PLD + wn * 64 + j * 16],
                                    acc[j], PLD, wmma::mem_row_major);
        __syncthreads();

        const float wq  = (float)(7 - (t >> 1));
        const bool updx = (t & 1) == 0;
        #pragma unroll
        for (int j = 0; j < 8; j++) {
            int oh = rt * PLD + ct0 + j * 32;
            int of = rt * 256 + ct0 + j * 32;
            float2 g0 = __half22float2(*(__half2*)&sP[oh]);
            float2 g1 = __half22float2(*(__half2*)&sP[oh + 2]);
            float4 hv = *(float4*)&sHv[of];
            hv.x += 0.005f * (fu[j*4+0] - g0.x);
            hv.y += 0.005f * (fu[j*4+1] - g0.y);
            hv.z += 0.005f * (fu[j*4+2] - g1.x);
            hv.w += 0.005f * (fu[j*4+3] - g1.y);
            *(float4*)&sHv[of] = hv;
            float4 hx = *(float4*)&sHx[of];
            if (updx) {
                hx.x += 0.01f * hv.x; hx.y += 0.01f * hv.y;
                hx.z += 0.01f * hv.z; hx.w += 0.01f * hv.w;
                *(float4*)&sHx[of] = hx;
            }
            float4 p;
            p.x = tanh_fast(hx.x) * hv.x * hv.x;
            p.y = tanh_fast(hx.y) * hv.y * hv.y;
            p.z = tanh_fast(hx.z) * hv.z * hv.z;
            p.w = tanh_fast(hx.w) * hv.w * hv.w;
            *(__half2*)&sP[oh]     = __floats2half2_rn(p.x, p.y);
            *(__half2*)&sP[oh + 2] = __floats2half2_rn(p.z, p.w);
            Sv[j*4+0] += p.x; Sv[j*4+1] += p.y; Sv[j*4+2] += p.z; Sv[j*4+3] += p.w;
            Sx[j*4+0] += wq * p.x; Sx[j*4+1] += wq * p.y;
            Sx[j*4+2] += wq * p.z; Sx[j*4+3] += wq * p.w;
        }
        __syncthreads();
    }

    #pragma unroll
    for (int j = 0; j < 8; j++) {
        size_t g = (size_t)(base + rt) * Rr + ct0 + j * 32;
        *(__half2*)(g_Svh + g)     = __floats2half2_rn(Sv[j*4+0], Sv[j*4+1]);
        *(__half2*)(g_Svh + g + 2) = __floats2half2_rn(Sv[j*4+2], Sv[j*4+3]);
        *(__half2*)(g_Sxh + g)     = __floats2half2_rn(Sx[j*4+0], Sx[j*4+1]);
        *(__half2*)(g_Sxh + g + 2) = __floats2half2_rn(Sx[j*4+2], Sx[j*4+3]);
    }
}

// ===========================================================================
// kFinal: dual fp16 GEMM (Sxh, Svh) @ Wh with fp16 accumulators, fused output.
// Tile 128x64, BK=64, grid (16,32), occupancy 2.
// ===========================================================================
constexpr int F_LDA = 72, F_LDB = 72, F_LDG = 72;
constexpr int F_STAGE_H = 2 * 128 * F_LDA + 64 * F_LDB;
constexpr int F_SMEM = 2 * F_STAGE_H * 2;

__global__ void __launch_bounds__(256, 2)
kFinal(const float* __restrict__ x0, const float* __restrict__ v0,
       const float* __restrict__ Fin, float* __restrict__ Xw, float* __restrict__ Vw)
{
    extern __shared__ __half smh[];
    const int bn = blockIdx.x, bm = blockIdx.y;
    const int tid = threadIdx.x, warp = tid >> 5;
    const int wRow = (warp & 3) * 32, wCol = (warp >> 2) * 32;

    AccHF acc[2][2][2];
    #pragma unroll
    for (int o = 0; o < 2; o++)
        #pragma unroll
        for (int i = 0; i < 2; i++)
            #pragma unroll
            for (int j = 0; j < 2; j++) wmma::fill_fragment(acc[o][i][j], (__half)0.0f);

    const __half* Ag[2] = { g_Sxh + (size_t)bm * 128 * Rr,
                            g_Svh + (size_t)bm * 128 * Rr };
    const __half* Bg = g_Wh + bn * 64;

    auto load_stage = [&](int kt, int s) {
        __half* st = smh + s * F_STAGE_H;
        const int k0 = kt * 64;
        #pragma unroll
        for (int o = 0; o < 2; o++) {
            __half* sA = st + o * 128 * F_LDA;
            #pragma unroll
            for (int it = 0; it < 4; it++) {
                int u = tid + it * 256;
                int r = u >> 3, c8 = u & 7;
                cp_async16(&sA[r * F_LDA + c8 * 8], Ag[o] + (size_t)r * Rr + k0 + c8 * 8);
            }
        }
        __half* sB = st + 2 * 128 * F_LDA;
        #pragma unroll
        for (int it = 0; it < 2; it++) {
            int u = tid + it * 256;
            int r = u >> 3, c8 = u & 7;
            cp_async16(&sB[r * F_LDB + c8 * 8], Bg + (size_t)(k0 + r) * Dd + c8 * 8);
        }
        cp_commit();
    };

    constexpr int KT = Rr / 64;
    load_stage(0, 0);
    for (int kt = 0; kt < KT; kt++) {
        if (kt + 1 < KT) { load_stage(kt + 1, (kt + 1) & 1); cp_wait<1>(); }
        else             { cp_wait<0>(); }
        __syncthreads();
        const __half* st = smh + (kt & 1) * F_STAGE_H;
        const __half* sB = st + 2 * 128 * F_LDA;
        #pragma unroll
        for (int kk = 0; kk < 4; kk++) {
            AH af[2][2]; BH bf[2];
            #pragma unroll
            for (int o = 0; o < 2; o++)
                #pragma unroll
                for (int i = 0; i < 2; i++)
                    wmma::load_matrix_sync(af[o][i],
                        st + o * 128 * F_LDA + (wRow + i * 16) * F_LDA + kk * 16, F_LDA);
            #pragma unroll
            for (int j = 0; j < 2; j++)
                wmma::load_matrix_sync(bf[j], sB + (kk * 16) * F_LDB + wCol + j * 16, F_LDB);
            #pragma unroll
            for (int o = 0; o < 2; o++)
                #pragma unroll
                for (int i = 0; i < 2; i++)
                    #pragma unroll
                    for (int j = 0; j < 2; j++)
                        wmma::mma_sync(acc[o][i][j], af[o][i], bf[j], acc[o][i][j]);
        }
        __syncthreads();
    }

    __half* sGx = smh;
    __half* sGv = smh + 128 * F_LDG;
    #pragma unroll
    for (int i = 0; i < 2; i++)
        #pragma unroll
        for (int j = 0; j < 2; j++) {
            wmma::store_matrix_sync(&sGx[(wRow + i * 16) * F_LDG + wCol + j * 16],
                                    acc[0][i][j], F_LDG, wmma::mem_row_major);
            wmma::store_matrix_sync(&sGv[(wRow + i * 16) * F_LDG + wCol + j * 16],
                                    acc[1][i][j], F_LDG, wmma::mem_row_major);
        }
    __syncthreads();

    const float c_xv = 0.08f;
    const float c_xf = 0.0032f;
    const float c_xg = 5e-5f;
    const float c_vf = 0.08f;
    const float c_vg = 0.005f;
    #pragma unroll
    for (int it = 0; it < 8; it++) {
        int u = tid + it * 256;
        int r = u >> 4, c4 = u & 15;
        float2 gx0 = __half22float2(*(__half2*)&sGx[r * F_LDG + c4 * 4]);
        float2 gx1 = __half22float2(*(__half2*)&sGx[r * F_LDG + c4 * 4 + 2]);
        float2 gv0 = __half22float2(*(__half2*)&sGv[r * F_LDG + c4 * 4]);
        float2 gv1 = __half22float2(*(__half2*)&sGv[r * F_LDG + c4 * 4 + 2]);
        size_t idx = (size_t)(bm * 128 + r) * Dd + bn * 64 + c4 * 4;
        float4 x = *(const float4*)(x0 + idx);
        float4 v = *(const float4*)(v0 + idx);
        float4 f = *(const float4*)(Fin + idx);
        float4 xo, vo;
        xo.x = x.x + c_xv * v.x + c_xf * f.x - c_xg * gx0.x;
        xo.y = x.y + c_xv * v.y + c_xf * f.y - c_xg * gx0.y;
        xo.z = x.z + c_xv * v.z + c_xf * f.z - c_xg * gx1.x;
        xo.w = x.w + c_xv * v.w + c_xf * f.w - c_xg * gx1.y;
        vo.x = v.x + c_vf * f.x - c_vg * gv0.x;
        vo.y = v.y + c_vf * f.y - c_vg * gv0.y;
        vo.z = v.z + c_vf * f.z - c_vg * gv1.x;
        vo.w = v.w + c_vf * f.w - c_vg * gv1.y;
        *(float4*)(Xw + idx) = xo;
        *(float4*)(Vw + idx) = vo;
    }
}

// ===========================================================================
extern "C" void kernel_launch(void* const* d_in, const int* in_sizes, int n_in,
                              void* d_out, int out_size)
{
    const float* x0 = (const float*)d_in[0];
    const float* v0 = (const float*)d_in[1];
    const float* F  = (const float*)d_in[2];
    const float* U  = (const float*)d_in[3];
    const float* W  = (const float*)d_in[4];

    float* Xw = (float*)d_out;
    float* Vw = Xw + (size_t)Bsz * Dd;

    cudaFuncSetAttribute(kWU,    cudaFuncAttributeMaxDynamicSharedMemorySize, W_SMEM);
    cudaFuncSetAttribute(kInit,  cudaFuncAttributeMaxDynamicSharedMemorySize, I_SMEM);
    cudaFuncSetAttribute(kSteps, cudaFuncAttributeMaxDynamicSharedMemorySize, (int)PS_SMEM);
    cudaFuncSetAttribute(kFinal, cudaFuncAttributeMaxDynamicSharedMemorySize, F_SMEM);

    void *pXh, *pVh, *pFh, *pUh, *pWh;
    cudaGetSymbolAddress(&pXh, g_Xh);
    cudaGetSymbolAddress(&pVh, g_Vh);
    cudaGetSymbolAddress(&pFh, g_Fh);
    cudaGetSymbolAddress(&pUh, g_Uh);
    cudaGetSymbolAddress(&pWh, g_Wh);

    const int nBD4 = Bsz * Dd / 4;
    const int nDR4 = Dd * Rr / 4;

    kCvt2<<<dim3(nDR4 / 256, 2), 256>>>((const float4*)U, (const float4*)W,
                                        (__half2*)pUh, (__half2*)pWh);

    dim3 blk(256);
    kWU<<<dim3(2, 2, 8), blk, W_SMEM>>>();
    kRed<<<Rr * Rr / 256, 256>>>();

    kCvt3<<<dim3(nBD4 / 256, 3), 256>>>((const float4*)x0, (const float4*)v0,
                                        (const float4*)F,
                                        (__half2*)pXh, (__half2*)pVh, (__half2*)pFh);

    kInit<<<dim3(4, 64), blk, I_SMEM>>>();
    kSteps<<<128, blk, PS_SMEM>>>();
    kFinal<<<dim3(16, 32), blk, F_SMEM>>>(x0, v0, F, Xw, Vw);
}